// round 6
// baseline (speedup 1.0000x reference)
#include <cuda_runtime.h>
#include <cstdint>
#include <cfloat>

#define NN 100000
#define EE 1600000
#define GG 64
#define HH 64

// ---------------- scratch (static device globals; no allocation) ----------------
__device__ int   g_is64;                    // 1 if index inputs are int64, 0 if int32
__device__ int   g_cnt[NN];
__device__ float g_dis[NN];
__device__ int   g_rowstart[NN + 1];
__device__ int2  g_csr[EE];                 // {col, __float_as_int(norm)}
__device__ float g_t1[(size_t)NN * 64];
__device__ float g_ts[(size_t)NN * 64];
__device__ float g_outb[(size_t)NN * 64];
__device__ float g_h[(size_t)NN * 64];
__device__ float g_sc[(size_t)NN * 64];
__device__ float g_stats[128];              // [0:64) sum, [64:128) sumsq
__device__ float g_pool[GG * HH];

// ---------------- index dtype detection + loader ----------------
__global__ void detect_kernel(const void* ei) {
    if (threadIdx.x == 0) {
        const long long* p = (const long long*)ei;
        int ok64 = 1;
        for (int e = 0; e < 256; e++) {
            long long v = p[e];
            if (v < 0 || v >= NN) { ok64 = 0; break; }
        }
        g_is64 = ok64;
    }
}

__device__ __forceinline__ int load_idx(const void* p, size_t i) {
    return g_is64 ? (int)((const long long*)p)[i] : ((const int*)p)[i];
}

// ---------------- init ----------------
__global__ void init_kernel() {
    int i = blockIdx.x * blockDim.x + threadIdx.x;
    if (i < NN) g_cnt[i] = 0;
    if (i < GG * HH) g_pool[i] = -FLT_MAX;
}

__global__ void zero_cnt_kernel() {
    int i = blockIdx.x * blockDim.x + threadIdx.x;
    if (i < NN) g_cnt[i] = 0;
}

__global__ void zstats_kernel() {
    if (threadIdx.x < 128) g_stats[threadIdx.x] = 0.0f;
}

// ---------------- degree histogram ----------------
__global__ void hist_kernel(const void* __restrict__ ei) {
    int e = blockIdx.x * blockDim.x + threadIdx.x;
    if (e < EE) {
        int r = load_idx(ei, e);
        if ((unsigned)r < NN) atomicAdd(&g_cnt[r], 1);
    }
}

__global__ void dis_kernel() {
    int i = blockIdx.x * blockDim.x + threadIdx.x;
    if (i < NN) {
        int d = g_cnt[i];
        g_dis[i] = (d > 0) ? rsqrtf((float)d) : 0.0f;
    }
}

// ---------------- exclusive scan over g_cnt -> g_rowstart ----------------
__device__ __forceinline__ int warp_scan_incl(int v, int lane) {
#pragma unroll
    for (int o = 1; o < 32; o <<= 1) {
        int t = __shfl_up_sync(0xffffffffu, v, o);
        if (lane >= o) v += t;
    }
    return v;
}

__global__ void scan_kernel() {
    __shared__ int wsum[32];
    __shared__ int carry;
    int tid = threadIdx.x, lane = tid & 31, wid = tid >> 5;
    if (tid == 0) carry = 0;
    __syncthreads();
    const int nch = (NN + 1023) >> 10;
    for (int ch = 0; ch < nch; ch++) {
        int i = (ch << 10) + tid;
        int v = (i < NN) ? g_cnt[i] : 0;
        int incl = warp_scan_incl(v, lane);
        if (lane == 31) wsum[wid] = incl;
        __syncthreads();
        if (wid == 0) {
            int s = wsum[lane];
            int si = warp_scan_incl(s, lane);
            wsum[lane] = si - s;            // exclusive warp offsets
        }
        __syncthreads();
        int excl = carry + wsum[wid] + incl - v;
        if (i < NN) g_rowstart[i] = excl;
        __syncthreads();
        if (tid == 1023) carry = excl + v;
        __syncthreads();
    }
    if (tid == 0) g_rowstart[NN] = carry;   // == EE
}

// ---------------- scatter edges into CSR (with norm) ----------------
__global__ void scatter_kernel(const void* __restrict__ ei) {
    int e = blockIdx.x * blockDim.x + threadIdx.x;
    if (e >= EE) return;
    int r = load_idx(ei, e);
    int c = load_idx(ei, (size_t)EE + e);
    if ((unsigned)r >= NN || (unsigned)c >= NN) return;
    int pos = g_rowstart[r] + atomicAdd(&g_cnt[r], 1);
    if ((unsigned)pos >= EE) return;
    float nm = -g_dis[r] * g_dis[c];
    g_csr[pos] = make_int2(c, __float_as_int(nm));
}

// ---------------- propagation: out[r] = sum_e norm * in[col_e]  (pull/gather) ----------------
__global__ void prop_kernel(const float* __restrict__ in, float* __restrict__ out) {
    int w = (blockIdx.x * blockDim.x + threadIdx.x) >> 5;
    int lane = threadIdx.x & 31;
    if (w >= NN) return;
    int s = g_rowstart[w];
    int e = g_rowstart[w + 1];
    float a0 = 0.f, a1 = 0.f, b0 = 0.f, b1 = 0.f;
    int j = s;
    for (; j + 2 <= e; j += 2) {
        int2 r0 = g_csr[j];
        int2 r1 = g_csr[j + 1];
        float2 v0 = *(const float2*)(in + (size_t)r0.x * 64 + lane * 2);
        float2 v1 = *(const float2*)(in + (size_t)r1.x * 64 + lane * 2);
        float n0 = __int_as_float(r0.y), n1 = __int_as_float(r1.y);
        a0 = fmaf(n0, v0.x, a0); a1 = fmaf(n0, v0.y, a1);
        b0 = fmaf(n1, v1.x, b0); b1 = fmaf(n1, v1.y, b1);
    }
    if (j < e) {
        int2 r0 = g_csr[j];
        float2 v0 = *(const float2*)(in + (size_t)r0.x * 64 + lane * 2);
        float n0 = __int_as_float(r0.y);
        a0 = fmaf(n0, v0.x, a0); a1 = fmaf(n0, v0.y, a1);
    }
    float2 o;
    o.x = a0 + b0;
    o.y = a1 + b1;
    *(float2*)(out + (size_t)w * 64 + lane * 2) = o;
}

// ---------------- fused GEMM:
// NM==3: out = A0@(W0-W2) + A1@W1 + A2@(2*W2) + bias   (ChebConv, Tx2 folded in)
// NM==1: out = A0@W + bias                              (shortcut)
// STATS: accumulate per-channel sum/sumsq into g_stats
template <int NM, bool STATS>
__global__ void __launch_bounds__(256) gemm_kernel(
    const float* __restrict__ A0, const float* __restrict__ A1, const float* __restrict__ A2,
    const float* __restrict__ W, const float* __restrict__ bias, float* __restrict__ out)
{
    extern __shared__ float sm[];
    float* w_s = sm;                       // NM*64*64
    float* a_s = sm + NM * 4096;           // 128*65
    float* st  = a_s + 128 * 65;           // 128
    const int tid = threadIdx.x;
    const int tc = tid & 15;               // column group (4 cols)
    const int tr = tid >> 4;               // row group (8 rows)
    const int rowBase = blockIdx.x * 128;

    for (int idx = tid; idx < NM * 4096; idx += 256) {
        float v;
        if (NM == 3) {
            int m = idx >> 12, r = idx & 4095;
            if (m == 0)      v = W[r] - W[8192 + r];
            else if (m == 1) v = W[4096 + r];
            else             v = 2.0f * W[8192 + r];
        } else {
            v = W[idx];
        }
        w_s[idx] = v;
    }

    float acc[8][4];
#pragma unroll
    for (int i = 0; i < 8; i++) {
        acc[i][0] = 0.f; acc[i][1] = 0.f; acc[i][2] = 0.f; acc[i][3] = 0.f;
    }

    const float* As[3] = {A0, A1, A2};
#pragma unroll
    for (int m = 0; m < NM; m++) {
        __syncthreads();
        const float* __restrict__ A = As[m];
        for (int idx = tid; idx < 2048; idx += 256) {
            int r = idx >> 4, q = idx & 15;
            int grow = rowBase + r;
            float4 v = make_float4(0.f, 0.f, 0.f, 0.f);
            if (grow < NN) v = *(const float4*)(A + (size_t)grow * 64 + q * 4);
            float* dst = a_s + r * 65 + q * 4;
            dst[0] = v.x; dst[1] = v.y; dst[2] = v.z; dst[3] = v.w;
        }
        __syncthreads();
        const float* wm = w_s + m * 4096;
#pragma unroll 8
        for (int k = 0; k < 64; k++) {
            const float4 wv = *(const float4*)(wm + k * 64 + tc * 4);
#pragma unroll
            for (int i = 0; i < 8; i++) {
                float a = a_s[(tr * 8 + i) * 65 + k];
                acc[i][0] = fmaf(a, wv.x, acc[i][0]);
                acc[i][1] = fmaf(a, wv.y, acc[i][1]);
                acc[i][2] = fmaf(a, wv.z, acc[i][2]);
                acc[i][3] = fmaf(a, wv.w, acc[i][3]);
            }
        }
    }

    const float4 bv = *(const float4*)(bias + tc * 4);
    if (STATS) {
        if (tid < 128) st[tid] = 0.0f;
        __syncthreads();
    }
    float s0 = 0.f, s1 = 0.f, s2 = 0.f, s3 = 0.f;
    float q0 = 0.f, q1 = 0.f, q2 = 0.f, q3 = 0.f;
#pragma unroll
    for (int i = 0; i < 8; i++) {
        int grow = rowBase + tr * 8 + i;
        if (grow < NN) {
            float o0 = acc[i][0] + bv.x, o1 = acc[i][1] + bv.y;
            float o2 = acc[i][2] + bv.z, o3 = acc[i][3] + bv.w;
            *(float4*)(out + (size_t)grow * 64 + tc * 4) = make_float4(o0, o1, o2, o3);
            if (STATS) {
                s0 += o0; s1 += o1; s2 += o2; s3 += o3;
                q0 = fmaf(o0, o0, q0); q1 = fmaf(o1, o1, q1);
                q2 = fmaf(o2, o2, q2); q3 = fmaf(o3, o3, q3);
            }
        }
    }
    if (STATS) {
        atomicAdd(&st[tc * 4 + 0], s0); atomicAdd(&st[tc * 4 + 1], s1);
        atomicAdd(&st[tc * 4 + 2], s2); atomicAdd(&st[tc * 4 + 3], s3);
        atomicAdd(&st[64 + tc * 4 + 0], q0); atomicAdd(&st[64 + tc * 4 + 1], q1);
        atomicAdd(&st[64 + tc * 4 + 2], q2); atomicAdd(&st[64 + tc * 4 + 3], q3);
        __syncthreads();
        if (tid < 128) atomicAdd(&g_stats[tid], st[tid]);
    }
}

// ---------------- BN + leakyReLU (+ optional shortcut add) ----------------
__global__ void norm_kernel(const float* __restrict__ in, const float* __restrict__ gam,
                            const float* __restrict__ bet, const float* __restrict__ sc,
                            float* __restrict__ oh)
{
    int i = blockIdx.x * blockDim.x + threadIdx.x;
    if (i >= NN * 16) return;
    int c0 = (i & 15) * 4;
    float4 v = *(const float4*)(in + (size_t)i * 4);
    float4 s4 = make_float4(0.f, 0.f, 0.f, 0.f);
    if (sc) s4 = *(const float4*)(sc + (size_t)i * 4);
    float vv[4] = {v.x, v.y, v.z, v.w};
    float ss[4] = {s4.x, s4.y, s4.z, s4.w};
    float o[4];
    const float invN = 1.0f / (float)NN;
#pragma unroll
    for (int j = 0; j < 4; j++) {
        int c = c0 + j;
        float mu  = g_stats[c] * invN;
        float var = g_stats[64 + c] * invN - mu * mu;
        float isd = rsqrtf(var + 1e-5f);
        float y = (vv[j] - mu) * isd * gam[c] + bet[c];
        y = (y > 0.0f) ? y : 0.01f * y;
        o[j] = y + ss[j];
    }
    *(float4*)(oh + (size_t)i * 4) = make_float4(o[0], o[1], o[2], o[3]);
}

// ---------------- segment max pooling (batch is sorted) ----------------
__device__ __forceinline__ void atomicMaxFloat(float* addr, float v) {
    if (v >= 0.0f) atomicMax((int*)addr, __float_as_int(v));
    else           atomicMin((unsigned int*)addr, __float_as_uint(v));
}

__global__ void pool_kernel(const float* __restrict__ h, const void* __restrict__ batch) {
    int tid = blockIdx.x * blockDim.x + threadIdx.x;
    int c = tid & 63;
    int chunk = tid >> 6;
    if (chunk >= (NN + 63) / 64) return;
    int n0 = chunk * 64;
    int n1 = (n0 + 64 < NN) ? (n0 + 64) : NN;
    int curg = -1;
    float curm = 0.0f;
    for (int n = n0; n < n1; n++) {
        int g = load_idx(batch, n);
        if ((unsigned)g >= GG) continue;
        float v = h[(size_t)n * 64 + c];
        if (g != curg) {
            if (curg >= 0) atomicMaxFloat(&g_pool[curg * 64 + c], curm);
            curg = g;
            curm = v;
        } else {
            curm = fmaxf(curm, v);
        }
    }
    if (curg >= 0) atomicMaxFloat(&g_pool[curg * 64 + c], curm);
}

// ---------------- final GEMV [G,H]@[H,1] + b ----------------
__global__ void final_kernel(const float* __restrict__ wlin, const float* __restrict__ blin,
                             float* __restrict__ outp)
{
    int g = threadIdx.x;
    if (g < GG) {
        float s = blin[0];
#pragma unroll
        for (int k = 0; k < HH; k++) s = fmaf(g_pool[g * 64 + k], wlin[k], s);
        outp[g] = s;
    }
}

// ---------------- launch ----------------
extern "C" void kernel_launch(void* const* d_in, const int* in_sizes, int n_in,
                              void* d_out, int out_size)
{
    const float* x       = (const float*)d_in[0];
    const void*  ei      = d_in[1];
    const void*  bat     = d_in[2];
    const float* w1  = (const float*)d_in[3];
    const float* b1  = (const float*)d_in[4];
    const float* w2  = (const float*)d_in[5];
    const float* b2  = (const float*)d_in[6];
    const float* w3  = (const float*)d_in[7];
    const float* b3  = (const float*)d_in[8];
    const float* g1  = (const float*)d_in[9];
    const float* be1 = (const float*)d_in[10];
    const float* g2  = (const float*)d_in[11];
    const float* be2 = (const float*)d_in[12];
    const float* g3  = (const float*)d_in[13];
    const float* be3 = (const float*)d_in[14];
    const float* wsc = (const float*)d_in[15];
    const float* bsc = (const float*)d_in[16];
    const float* wl  = (const float*)d_in[17];
    const float* bl  = (const float*)d_in[18];
    float* outp = (float*)d_out;

    float *p_t1, *p_ts, *p_out, *p_h, *p_sc;
    cudaGetSymbolAddress((void**)&p_t1,  g_t1);
    cudaGetSymbolAddress((void**)&p_ts,  g_ts);
    cudaGetSymbolAddress((void**)&p_out, g_outb);
    cudaGetSymbolAddress((void**)&p_h,   g_h);
    cudaGetSymbolAddress((void**)&p_sc,  g_sc);

    const int smem3 = (3 * 4096 + 128 * 65 + 128) * (int)sizeof(float);
    const int smem1 = (1 * 4096 + 128 * 65 + 128) * (int)sizeof(float);
    cudaFuncSetAttribute(gemm_kernel<3, true>,  cudaFuncAttributeMaxDynamicSharedMemorySize, smem3);
    cudaFuncSetAttribute(gemm_kernel<1, false>, cudaFuncAttributeMaxDynamicSharedMemorySize, smem1);

    const int TB = 256;
    const int gridN  = (NN + TB - 1) / TB;
    const int gridE  = (EE + TB - 1) / TB;
    const int gridP  = (NN * 32 + TB - 1) / TB;       // warp per node
    const int gridG  = (NN + 127) / 128;              // gemm tiles
    const int gridNm = (NN * 16 + TB - 1) / TB;       // normalize (float4)
    const int gridPl = (((NN + 63) / 64) * 64 + TB - 1) / TB;

    // dtype detect + graph structure (recomputed every launch; deterministic)
    detect_kernel<<<1, 32>>>(ei);
    init_kernel<<<gridN, TB>>>();
    hist_kernel<<<gridE, TB>>>(ei);
    dis_kernel<<<gridN, TB>>>();
    scan_kernel<<<1, 1024>>>();
    zero_cnt_kernel<<<gridN, TB>>>();
    scatter_kernel<<<gridE, TB>>>(ei);

    // shortcut: sc = x @ w_sc + b_sc
    gemm_kernel<1, false><<<gridG, TB, smem1>>>(x, x, x, wsc, bsc, p_sc);

    // layer 1 (input x)
    prop_kernel<<<gridP, TB>>>(x, p_t1);
    prop_kernel<<<gridP, TB>>>(p_t1, p_ts);
    zstats_kernel<<<1, 128>>>();
    gemm_kernel<3, true><<<gridG, TB, smem3>>>(x, p_t1, p_ts, w1, b1, p_out);
    norm_kernel<<<gridNm, TB>>>(p_out, g1, be1, nullptr, p_h);

    // layer 2
    prop_kernel<<<gridP, TB>>>(p_h, p_t1);
    prop_kernel<<<gridP, TB>>>(p_t1, p_ts);
    zstats_kernel<<<1, 128>>>();
    gemm_kernel<3, true><<<gridG, TB, smem3>>>(p_h, p_t1, p_ts, w2, b2, p_out);
    norm_kernel<<<gridNm, TB>>>(p_out, g2, be2, nullptr, p_h);

    // layer 3 (+ shortcut)
    prop_kernel<<<gridP, TB>>>(p_h, p_t1);
    prop_kernel<<<gridP, TB>>>(p_t1, p_ts);
    zstats_kernel<<<1, 128>>>();
    gemm_kernel<3, true><<<gridG, TB, smem3>>>(p_h, p_t1, p_ts, w3, b3, p_out);
    norm_kernel<<<gridNm, TB>>>(p_out, g3, be3, p_sc, p_h);

    // pool + head
    pool_kernel<<<gridPl, TB>>>(p_h, bat);
    final_kernel<<<1, 64>>>(wl, bl, outp);
}

// round 9
// speedup vs baseline: 1.2943x; 1.2943x over previous
#include <cuda_runtime.h>
#include <cstdint>
#include <cfloat>

#define NN 100000
#define EE 1600000
#define GG 64
#define HH 64

// ---------------- scratch (static device globals; no allocation) ----------------
__device__ int   g_is64;                    // 1 if index inputs are int64, 0 if int32
__device__ int   g_cnt[NN];
__device__ float g_dis[NN];
__device__ int   g_rowstart[NN + 1];
__device__ int2  g_csr[EE];                 // {col, __float_as_int(norm)}
__device__ float g_t1[(size_t)NN * 64];
__device__ float g_ts[(size_t)NN * 64];
__device__ float g_outb[(size_t)NN * 64];
__device__ float g_h[(size_t)NN * 64];
__device__ float g_sc[(size_t)NN * 64];
__device__ float g_stats[128];              // [0:64) sum, [64:128) sumsq
__device__ float g_pool[GG * HH];

__device__ __forceinline__ int load_idx(const void* p, size_t i) {
    return g_is64 ? (int)((const long long*)p)[i] : ((const int*)p)[i];
}

// ---------------- init (+ dtype detection folded in) ----------------
__global__ void init_kernel(const void* ei) {
    int i = blockIdx.x * blockDim.x + threadIdx.x;
    if (i == 0) {
        const long long* p = (const long long*)ei;
        int ok64 = 1;
        for (int e = 0; e < 256; e++) {
            long long v = p[e];
            if (v < 0 || v >= NN) { ok64 = 0; break; }
        }
        g_is64 = ok64;
    }
    if (i < NN) g_cnt[i] = 0;
    if (i < GG * HH) g_pool[i] = -FLT_MAX;
}

// ---------------- degree histogram ----------------
__global__ void hist_kernel(const void* __restrict__ ei) {
    int e = blockIdx.x * blockDim.x + threadIdx.x;
    if (e < EE) {
        int r = load_idx(ei, e);
        if ((unsigned)r < NN) atomicAdd(&g_cnt[r], 1);
    }
}

__global__ void dis_kernel() {
    int i = blockIdx.x * blockDim.x + threadIdx.x;
    if (i < NN) {
        int d = g_cnt[i];
        g_dis[i] = (d > 0) ? rsqrtf((float)d) : 0.0f;
    }
}

// ---------------- exclusive scan over g_cnt -> g_rowstart (+ cnt reset folded in) ----------------
__device__ __forceinline__ int warp_scan_incl(int v, int lane) {
#pragma unroll
    for (int o = 1; o < 32; o <<= 1) {
        int t = __shfl_up_sync(0xffffffffu, v, o);
        if (lane >= o) v += t;
    }
    return v;
}

__global__ void scan_kernel() {
    __shared__ int wsum[32];
    __shared__ int carry;
    int tid = threadIdx.x, lane = tid & 31, wid = tid >> 5;
    if (tid == 0) carry = 0;
    __syncthreads();
    const int nch = (NN + 1023) >> 10;
    for (int ch = 0; ch < nch; ch++) {
        int i = (ch << 10) + tid;
        int v = (i < NN) ? g_cnt[i] : 0;
        if (i < NN) g_cnt[i] = 0;           // reset for scatter's cursor
        int incl = warp_scan_incl(v, lane);
        if (lane == 31) wsum[wid] = incl;
        __syncthreads();
        if (wid == 0) {
            int s = wsum[lane];
            int si = warp_scan_incl(s, lane);
            wsum[lane] = si - s;            // exclusive warp offsets
        }
        __syncthreads();
        int excl = carry + wsum[wid] + incl - v;
        if (i < NN) g_rowstart[i] = excl;
        __syncthreads();
        if (tid == 1023) carry = excl + v;
        __syncthreads();
    }
    if (tid == 0) g_rowstart[NN] = carry;   // == EE
}

// ---------------- scatter edges into CSR (with norm) ----------------
__global__ void scatter_kernel(const void* __restrict__ ei) {
    int e = blockIdx.x * blockDim.x + threadIdx.x;
    if (e >= EE) return;
    int r = load_idx(ei, e);
    int c = load_idx(ei, (size_t)EE + e);
    if ((unsigned)r >= NN || (unsigned)c >= NN) return;
    int pos = g_rowstart[r] + atomicAdd(&g_cnt[r], 1);
    if ((unsigned)pos >= EE) return;
    float nm = -g_dis[r] * g_dis[c];
    g_csr[pos] = make_int2(c, __float_as_int(nm));
}

// ---------------- propagation: out[r] = sum_e norm * in[col_e]  (pull/gather) ----------------
// Warp per node. Two 16-lane halves each cover the full 64-float row via float4
// (one LDG.128 per lane); half 0 takes even edges, half 1 odd edges of the SAME
// node (no divergence). Unroll x2 -> 4 independent 128b gathers in flight.
// Also zeroes g_stats for the following GEMM's BN accumulation.
__global__ void prop_kernel(const float* __restrict__ in, float* __restrict__ out) {
    if (blockIdx.x == 0 && threadIdx.x < 128) g_stats[threadIdx.x] = 0.0f;
    int w = (blockIdx.x * blockDim.x + threadIdx.x) >> 5;
    if (w >= NN) return;
    int lane = threadIdx.x & 31;
    int sub = lane >> 4;             // which half
    int lc  = lane & 15;             // feature quad within row
    int s = g_rowstart[w];
    int e = g_rowstart[w + 1];
    float4 a0 = make_float4(0.f, 0.f, 0.f, 0.f);
    float4 a1 = make_float4(0.f, 0.f, 0.f, 0.f);
    int j = s + sub;
    for (; j + 2 < e; j += 4) {
        int2 r0 = g_csr[j];
        int2 r1 = g_csr[j + 2];
        float4 v0 = *(const float4*)(in + (size_t)r0.x * 64 + lc * 4);
        float4 v1 = *(const float4*)(in + (size_t)r1.x * 64 + lc * 4);
        float n0 = __int_as_float(r0.y), n1 = __int_as_float(r1.y);
        a0.x = fmaf(n0, v0.x, a0.x); a0.y = fmaf(n0, v0.y, a0.y);
        a0.z = fmaf(n0, v0.z, a0.z); a0.w = fmaf(n0, v0.w, a0.w);
        a1.x = fmaf(n1, v1.x, a1.x); a1.y = fmaf(n1, v1.y, a1.y);
        a1.z = fmaf(n1, v1.z, a1.z); a1.w = fmaf(n1, v1.w, a1.w);
    }
    if (j < e) {
        int2 r0 = g_csr[j];
        float4 v0 = *(const float4*)(in + (size_t)r0.x * 64 + lc * 4);
        float n0 = __int_as_float(r0.y);
        a0.x = fmaf(n0, v0.x, a0.x); a0.y = fmaf(n0, v0.y, a0.y);
        a0.z = fmaf(n0, v0.z, a0.z); a0.w = fmaf(n0, v0.w, a0.w);
    }
    a0.x += a1.x; a0.y += a1.y; a0.z += a1.z; a0.w += a1.w;
    // combine the two halves
    a0.x += __shfl_down_sync(0xffffffffu, a0.x, 16);
    a0.y += __shfl_down_sync(0xffffffffu, a0.y, 16);
    a0.z += __shfl_down_sync(0xffffffffu, a0.z, 16);
    a0.w += __shfl_down_sync(0xffffffffu, a0.w, 16);
    if (sub == 0)
        *(float4*)(out + (size_t)w * 64 + lc * 4) = a0;
}

// ---------------- fused GEMM:
// NM==3: out = A0@(W0-W2) + A1@W1 + A2@(2*W2) + bias   (ChebConv, Tx2 folded in)
// NM==1: out = A0@W + bias                              (shortcut)
// STATS: accumulate per-channel sum/sumsq into g_stats
template <int NM, bool STATS>
__global__ void __launch_bounds__(256) gemm_kernel(
    const float* __restrict__ A0, const float* __restrict__ A1, const float* __restrict__ A2,
    const float* __restrict__ W, const float* __restrict__ bias, float* __restrict__ out)
{
    extern __shared__ float sm[];
    float* w_s = sm;                       // NM*64*64
    float* a_s = sm + NM * 4096;           // 128*65
    float* st  = a_s + 128 * 65;           // 128
    const int tid = threadIdx.x;
    const int tc = tid & 15;               // column group (4 cols)
    const int tr = tid >> 4;               // row group (8 rows)
    const int rowBase = blockIdx.x * 128;

    for (int idx = tid; idx < NM * 4096; idx += 256) {
        float v;
        if (NM == 3) {
            int m = idx >> 12, r = idx & 4095;
            if (m == 0)      v = W[r] - W[8192 + r];
            else if (m == 1) v = W[4096 + r];
            else             v = 2.0f * W[8192 + r];
        } else {
            v = W[idx];
        }
        w_s[idx] = v;
    }

    float acc[8][4];
#pragma unroll
    for (int i = 0; i < 8; i++) {
        acc[i][0] = 0.f; acc[i][1] = 0.f; acc[i][2] = 0.f; acc[i][3] = 0.f;
    }

    const float* As[3] = {A0, A1, A2};
#pragma unroll
    for (int m = 0; m < NM; m++) {
        __syncthreads();
        const float* __restrict__ A = As[m];
        for (int idx = tid; idx < 2048; idx += 256) {
            int r = idx >> 4, q = idx & 15;
            int grow = rowBase + r;
            float4 v = make_float4(0.f, 0.f, 0.f, 0.f);
            if (grow < NN) v = *(const float4*)(A + (size_t)grow * 64 + q * 4);
            float* dst = a_s + r * 65 + q * 4;
            dst[0] = v.x; dst[1] = v.y; dst[2] = v.z; dst[3] = v.w;
        }
        __syncthreads();
        const float* wm = w_s + m * 4096;
#pragma unroll 8
        for (int k = 0; k < 64; k++) {
            const float4 wv = *(const float4*)(wm + k * 64 + tc * 4);
#pragma unroll
            for (int i = 0; i < 8; i++) {
                float a = a_s[(tr * 8 + i) * 65 + k];
                acc[i][0] = fmaf(a, wv.x, acc[i][0]);
                acc[i][1] = fmaf(a, wv.y, acc[i][1]);
                acc[i][2] = fmaf(a, wv.z, acc[i][2]);
                acc[i][3] = fmaf(a, wv.w, acc[i][3]);
            }
        }
    }

    const float4 bv = *(const float4*)(bias + tc * 4);
    if (STATS) {
        if (tid < 128) st[tid] = 0.0f;
        __syncthreads();
    }
    float s0 = 0.f, s1 = 0.f, s2 = 0.f, s3 = 0.f;
    float q0 = 0.f, q1 = 0.f, q2 = 0.f, q3 = 0.f;
#pragma unroll
    for (int i = 0; i < 8; i++) {
        int grow = rowBase + tr * 8 + i;
        if (grow < NN) {
            float o0 = acc[i][0] + bv.x, o1 = acc[i][1] + bv.y;
            float o2 = acc[i][2] + bv.z, o3 = acc[i][3] + bv.w;
            *(float4*)(out + (size_t)grow * 64 + tc * 4) = make_float4(o0, o1, o2, o3);
            if (STATS) {
                s0 += o0; s1 += o1; s2 += o2; s3 += o3;
                q0 = fmaf(o0, o0, q0); q1 = fmaf(o1, o1, q1);
                q2 = fmaf(o2, o2, q2); q3 = fmaf(o3, o3, q3);
            }
        }
    }
    if (STATS) {
        atomicAdd(&st[tc * 4 + 0], s0); atomicAdd(&st[tc * 4 + 1], s1);
        atomicAdd(&st[tc * 4 + 2], s2); atomicAdd(&st[tc * 4 + 3], s3);
        atomicAdd(&st[64 + tc * 4 + 0], q0); atomicAdd(&st[64 + tc * 4 + 1], q1);
        atomicAdd(&st[64 + tc * 4 + 2], q2); atomicAdd(&st[64 + tc * 4 + 3], q3);
        __syncthreads();
        if (tid < 128) atomicAdd(&g_stats[tid], st[tid]);
    }
}

// ---------------- BN + leakyReLU (+ optional shortcut add) ----------------
__global__ void norm_kernel(const float* __restrict__ in, const float* __restrict__ gam,
                            const float* __restrict__ bet, const float* __restrict__ sc,
                            float* __restrict__ oh)
{
    int i = blockIdx.x * blockDim.x + threadIdx.x;
    if (i >= NN * 16) return;
    int c0 = (i & 15) * 4;
    float4 v = *(const float4*)(in + (size_t)i * 4);
    float4 s4 = make_float4(0.f, 0.f, 0.f, 0.f);
    if (sc) s4 = *(const float4*)(sc + (size_t)i * 4);
    float vv[4] = {v.x, v.y, v.z, v.w};
    float ss[4] = {s4.x, s4.y, s4.z, s4.w};
    float o[4];
    const float invN = 1.0f / (float)NN;
#pragma unroll
    for (int j = 0; j < 4; j++) {
        int c = c0 + j;
        float mu  = g_stats[c] * invN;
        float var = g_stats[64 + c] * invN - mu * mu;
        float isd = rsqrtf(var + 1e-5f);
        float y = (vv[j] - mu) * isd * gam[c] + bet[c];
        y = (y > 0.0f) ? y : 0.01f * y;
        o[j] = y + ss[j];
    }
    *(float4*)(oh + (size_t)i * 4) = make_float4(o[0], o[1], o[2], o[3]);
}

// ---------------- segment max pooling (batch is sorted) ----------------
__device__ __forceinline__ void atomicMaxFloat(float* addr, float v) {
    if (v >= 0.0f) atomicMax((int*)addr, __float_as_int(v));
    else           atomicMin((unsigned int*)addr, __float_as_uint(v));
}

__global__ void pool_kernel(const float* __restrict__ h, const void* __restrict__ batch) {
    int tid = blockIdx.x * blockDim.x + threadIdx.x;
    int c = tid & 63;
    int chunk = tid >> 6;
    if (chunk >= (NN + 63) / 64) return;
    int n0 = chunk * 64;
    int n1 = (n0 + 64 < NN) ? (n0 + 64) : NN;
    int curg = -1;
    float curm = 0.0f;
    for (int n = n0; n < n1; n++) {
        int g = load_idx(batch, n);
        if ((unsigned)g >= GG) continue;
        float v = h[(size_t)n * 64 + c];
        if (g != curg) {
            if (curg >= 0) atomicMaxFloat(&g_pool[curg * 64 + c], curm);
            curg = g;
            curm = v;
        } else {
            curm = fmaxf(curm, v);
        }
    }
    if (curg >= 0) atomicMaxFloat(&g_pool[curg * 64 + c], curm);
}

// ---------------- final GEMV [G,H]@[H,1] + b ----------------
__global__ void final_kernel(const float* __restrict__ wlin, const float* __restrict__ blin,
                             float* __restrict__ outp)
{
    int g = threadIdx.x;
    if (g < GG) {
        float s = blin[0];
#pragma unroll
        for (int k = 0; k < HH; k++) s = fmaf(g_pool[g * 64 + k], wlin[k], s);
        outp[g] = s;
    }
}

// ---------------- launch ----------------
extern "C" void kernel_launch(void* const* d_in, const int* in_sizes, int n_in,
                              void* d_out, int out_size)
{
    const float* x       = (const float*)d_in[0];
    const void*  ei      = d_in[1];
    const void*  bat     = d_in[2];
    const float* w1  = (const float*)d_in[3];
    const float* b1  = (const float*)d_in[4];
    const float* w2  = (const float*)d_in[5];
    const float* b2  = (const float*)d_in[6];
    const float* w3  = (const float*)d_in[7];
    const float* b3  = (const float*)d_in[8];
    const float* g1  = (const float*)d_in[9];
    const float* be1 = (const float*)d_in[10];
    const float* g2  = (const float*)d_in[11];
    const float* be2 = (const float*)d_in[12];
    const float* g3  = (const float*)d_in[13];
    const float* be3 = (const float*)d_in[14];
    const float* wsc = (const float*)d_in[15];
    const float* bsc = (const float*)d_in[16];
    const float* wl  = (const float*)d_in[17];
    const float* bl  = (const float*)d_in[18];
    float* outp = (float*)d_out;

    float *p_t1, *p_ts, *p_out, *p_h, *p_sc;
    cudaGetSymbolAddress((void**)&p_t1,  g_t1);
    cudaGetSymbolAddress((void**)&p_ts,  g_ts);
    cudaGetSymbolAddress((void**)&p_out, g_outb);
    cudaGetSymbolAddress((void**)&p_h,   g_h);
    cudaGetSymbolAddress((void**)&p_sc,  g_sc);

    const int smem3 = (3 * 4096 + 128 * 65 + 128) * (int)sizeof(float);
    const int smem1 = (1 * 4096 + 128 * 65 + 128) * (int)sizeof(float);
    cudaFuncSetAttribute(gemm_kernel<3, true>,  cudaFuncAttributeMaxDynamicSharedMemorySize, smem3);
    cudaFuncSetAttribute(gemm_kernel<1, false>, cudaFuncAttributeMaxDynamicSharedMemorySize, smem1);

    const int TB = 256;
    const int gridN  = (NN + TB - 1) / TB;
    const int gridE  = (EE + TB - 1) / TB;
    const int gridP  = (NN * 32 + TB - 1) / TB;       // warp per node
    const int gridG  = (NN + 127) / 128;              // gemm tiles
    const int gridNm = (NN * 16 + TB - 1) / TB;       // normalize (float4)
    const int gridPl = (((NN + 63) / 64) * 64 + TB - 1) / TB;

    // graph structure (recomputed every launch; deterministic work)
    init_kernel<<<gridN, TB>>>(ei);                    // 1 (detect folded in)
    hist_kernel<<<gridE, TB>>>(ei);                    // 2
    dis_kernel<<<gridN, TB>>>();                       // 3
    scan_kernel<<<1, 1024>>>();                        // 4 (cnt reset folded in)
    scatter_kernel<<<gridE, TB>>>(ei);                 // 5

    // layer 1 (input x)            -- 6th launch = prop (ncu -s 5 -c 1 target)
    prop_kernel<<<gridP, TB>>>(x, p_t1);
    prop_kernel<<<gridP, TB>>>(p_t1, p_ts);
    gemm_kernel<3, true><<<gridG, TB, smem3>>>(x, p_t1, p_ts, w1, b1, p_out);
    norm_kernel<<<gridNm, TB>>>(p_out, g1, be1, nullptr, p_h);

    // layer 2
    prop_kernel<<<gridP, TB>>>(p_h, p_t1);
    prop_kernel<<<gridP, TB>>>(p_t1, p_ts);
    gemm_kernel<3, true><<<gridG, TB, smem3>>>(p_h, p_t1, p_ts, w2, b2, p_out);
    norm_kernel<<<gridNm, TB>>>(p_out, g2, be2, nullptr, p_h);

    // layer 3 (+ shortcut)
    prop_kernel<<<gridP, TB>>>(p_h, p_t1);
    prop_kernel<<<gridP, TB>>>(p_t1, p_ts);
    gemm_kernel<3, true><<<gridG, TB, smem3>>>(p_h, p_t1, p_ts, w3, b3, p_out);
    gemm_kernel<1, false><<<gridG, TB, smem1>>>(x, x, x, wsc, bsc, p_sc);
    norm_kernel<<<gridNm, TB>>>(p_out, g3, be3, p_sc, p_h);

    // pool + head
    pool_kernel<<<gridPl, TB>>>(p_h, bat);
    final_kernel<<<1, 64>>>(wl, bl, outp);
}

// round 10
// speedup vs baseline: 1.4264x; 1.1020x over previous
#include <cuda_runtime.h>
#include <cstdint>
#include <cfloat>

#define NN 100000
#define EE 1600000
#define GG 64
#define HH 64

#define SCAN_IT 16
#define SCAN_CHUNK 4096
#define SCAN_NB 25              // ceil(NN / SCAN_CHUNK)

// ---------------- scratch (static device globals; no allocation) ----------------
__device__ int   g_is64;                    // 1 if index inputs are int64, 0 if int32
__device__ int   g_cnt[NN];
__device__ float g_dis[NN];
__device__ int   g_rowstart[NN + 1];
__device__ int   g_bsum[SCAN_NB];
__device__ int   g_bflag[SCAN_NB];
__device__ int2  g_csr[EE];                 // {col, __float_as_int(norm)}
__device__ float g_t1[(size_t)NN * 64];
__device__ float g_ts[(size_t)NN * 64];
__device__ float g_outb[(size_t)NN * 64];
__device__ float g_h[(size_t)NN * 64];
__device__ float g_sc[(size_t)NN * 64];
__device__ float g_stats[128];              // [0:64) sum, [64:128) sumsq
__device__ float g_pool[GG * HH];

__device__ __forceinline__ int load_idx(const void* p, size_t i) {
    return g_is64 ? (int)((const long long*)p)[i] : ((const int*)p)[i];
}

// ---------------- init (+ dtype detection folded in) ----------------
__global__ void init_kernel(const void* ei) {
    int i = blockIdx.x * blockDim.x + threadIdx.x;
    if (i == 0) {
        const long long* p = (const long long*)ei;
        int ok64 = 1;
        for (int e = 0; e < 256; e++) {
            long long v = p[e];
            if (v < 0 || v >= NN) { ok64 = 0; break; }
        }
        g_is64 = ok64;
    }
    if (i < NN) g_cnt[i] = 0;
    if (i < GG * HH) g_pool[i] = -FLT_MAX;
    if (i < SCAN_NB) g_bflag[i] = 0;
}

// ---------------- degree histogram ----------------
__global__ void hist_kernel(const void* __restrict__ ei) {
    int e = blockIdx.x * blockDim.x + threadIdx.x;
    if (e < EE) {
        int r = load_idx(ei, e);
        if ((unsigned)r < NN) atomicAdd(&g_cnt[r], 1);
    }
}

// ---------------- parallel scan: g_cnt -> g_rowstart (exclusive) ----------------
// 25 blocks x 256 threads x 16 items. Chained carry across blocks via
// g_bsum/g_bflag (reset each launch by init_kernel). Also computes g_dis
// (deg^-1/2) and resets g_cnt for scatter's cursor.
__device__ __forceinline__ int warp_scan_incl(int v, int lane) {
#pragma unroll
    for (int o = 1; o < 32; o <<= 1) {
        int t = __shfl_up_sync(0xffffffffu, v, o);
        if (lane >= o) v += t;
    }
    return v;
}

__global__ void __launch_bounds__(256) scan_kernel() {
    __shared__ int wtot[8];
    __shared__ int s_prefix;
    const int bid = blockIdx.x, tid = threadIdx.x;
    const int lane = tid & 31, wid = tid >> 5;
    const int base = bid * SCAN_CHUNK + tid * SCAN_IT;

    int v[SCAN_IT];
    int tsum = 0;
#pragma unroll
    for (int i = 0; i < SCAN_IT; i++) {
        int idx = base + i;
        int val = 0;
        if (idx < NN) {
            val = g_cnt[idx];
            g_cnt[idx] = 0;
            g_dis[idx] = (val > 0) ? rsqrtf((float)val) : 0.0f;
        }
        v[i] = tsum;            // exclusive within thread
        tsum += val;
    }
    int incl = warp_scan_incl(tsum, lane);
    if (lane == 31) wtot[wid] = incl;
    __syncthreads();
    if (wid == 0) {
        int s = (lane < 8) ? wtot[lane] : 0;
        int si = warp_scan_incl(s, lane);
        if (lane < 8) wtot[lane] = si;
    }
    __syncthreads();
    int warpExcl = wid ? wtot[wid - 1] : 0;
    int threadExcl = warpExcl + incl - tsum;
    int blockTot = wtot[7];

    if (tid == 0) {
        int prefix = 0;
        if (bid > 0) {
            while (atomicAdd(&g_bflag[bid - 1], 0) == 0) { }
            prefix = g_bsum[bid - 1];
        }
        g_bsum[bid] = prefix + blockTot;
        __threadfence();
        atomicExch(&g_bflag[bid], 1);
        s_prefix = prefix;
        if (bid == SCAN_NB - 1) g_rowstart[NN] = prefix + blockTot;  // == EE
    }
    __syncthreads();
    int pref = s_prefix + threadExcl;
#pragma unroll
    for (int i = 0; i < SCAN_IT; i++) {
        int idx = base + i;
        if (idx < NN) g_rowstart[idx] = pref + v[i];
    }
}

// ---------------- scatter edges into CSR (with norm) ----------------
__global__ void scatter_kernel(const void* __restrict__ ei) {
    int e = blockIdx.x * blockDim.x + threadIdx.x;
    if (e >= EE) return;
    int r = load_idx(ei, e);
    int c = load_idx(ei, (size_t)EE + e);
    if ((unsigned)r >= NN || (unsigned)c >= NN) return;
    int pos = g_rowstart[r] + atomicAdd(&g_cnt[r], 1);
    if ((unsigned)pos >= EE) return;
    float nm = -g_dis[r] * g_dis[c];
    g_csr[pos] = make_int2(c, __float_as_int(nm));
}

// ---------------- propagation: out[r] = sum_e norm * in[col_e]  (pull/gather) ----------------
__global__ void prop_kernel(const float* __restrict__ in, float* __restrict__ out) {
    if (blockIdx.x == 0 && threadIdx.x < 128) g_stats[threadIdx.x] = 0.0f;
    int w = (blockIdx.x * blockDim.x + threadIdx.x) >> 5;
    if (w >= NN) return;
    int lane = threadIdx.x & 31;
    int sub = lane >> 4;             // which half
    int lc  = lane & 15;             // feature quad within row
    int s = g_rowstart[w];
    int e = g_rowstart[w + 1];
    float4 a0 = make_float4(0.f, 0.f, 0.f, 0.f);
    float4 a1 = make_float4(0.f, 0.f, 0.f, 0.f);
    int j = s + sub;
    for (; j + 2 < e; j += 4) {
        int2 r0 = g_csr[j];
        int2 r1 = g_csr[j + 2];
        float4 v0 = *(const float4*)(in + (size_t)r0.x * 64 + lc * 4);
        float4 v1 = *(const float4*)(in + (size_t)r1.x * 64 + lc * 4);
        float n0 = __int_as_float(r0.y), n1 = __int_as_float(r1.y);
        a0.x = fmaf(n0, v0.x, a0.x); a0.y = fmaf(n0, v0.y, a0.y);
        a0.z = fmaf(n0, v0.z, a0.z); a0.w = fmaf(n0, v0.w, a0.w);
        a1.x = fmaf(n1, v1.x, a1.x); a1.y = fmaf(n1, v1.y, a1.y);
        a1.z = fmaf(n1, v1.z, a1.z); a1.w = fmaf(n1, v1.w, a1.w);
    }
    if (j < e) {
        int2 r0 = g_csr[j];
        float4 v0 = *(const float4*)(in + (size_t)r0.x * 64 + lc * 4);
        float n0 = __int_as_float(r0.y);
        a0.x = fmaf(n0, v0.x, a0.x); a0.y = fmaf(n0, v0.y, a0.y);
        a0.z = fmaf(n0, v0.z, a0.z); a0.w = fmaf(n0, v0.w, a0.w);
    }
    a0.x += a1.x; a0.y += a1.y; a0.z += a1.z; a0.w += a1.w;
    a0.x += __shfl_down_sync(0xffffffffu, a0.x, 16);
    a0.y += __shfl_down_sync(0xffffffffu, a0.y, 16);
    a0.z += __shfl_down_sync(0xffffffffu, a0.z, 16);
    a0.w += __shfl_down_sync(0xffffffffu, a0.w, 16);
    if (sub == 0)
        *(float4*)(out + (size_t)w * 64 + lc * 4) = a0;
}

// ---------------- fused GEMM:
// NM==3: out = A0@(W0-W2) + A1@W1 + A2@(2*W2) + bias   (ChebConv, Tx2 folded in)
// NM==1: out = A0@W + bias                              (shortcut)
// STATS: accumulate per-channel sum/sumsq into g_stats
template <int NM, bool STATS>
__global__ void __launch_bounds__(256) gemm_kernel(
    const float* __restrict__ A0, const float* __restrict__ A1, const float* __restrict__ A2,
    const float* __restrict__ W, const float* __restrict__ bias, float* __restrict__ out)
{
    extern __shared__ float sm[];
    float* w_s = sm;                       // NM*64*64
    float* a_s = sm + NM * 4096;           // 128*65
    float* st  = a_s + 128 * 65;           // 128
    const int tid = threadIdx.x;
    const int tc = tid & 15;               // column group (4 cols)
    const int tr = tid >> 4;               // row group (8 rows)
    const int rowBase = blockIdx.x * 128;

    for (int idx = tid; idx < NM * 4096; idx += 256) {
        float v;
        if (NM == 3) {
            int m = idx >> 12, r = idx & 4095;
            if (m == 0)      v = W[r] - W[8192 + r];
            else if (m == 1) v = W[4096 + r];
            else             v = 2.0f * W[8192 + r];
        } else {
            v = W[idx];
        }
        w_s[idx] = v;
    }

    float acc[8][4];
#pragma unroll
    for (int i = 0; i < 8; i++) {
        acc[i][0] = 0.f; acc[i][1] = 0.f; acc[i][2] = 0.f; acc[i][3] = 0.f;
    }

    const float* As[3] = {A0, A1, A2};
#pragma unroll
    for (int m = 0; m < NM; m++) {
        __syncthreads();
        const float* __restrict__ A = As[m];
        for (int idx = tid; idx < 2048; idx += 256) {
            int r = idx >> 4, q = idx & 15;
            int grow = rowBase + r;
            float4 v = make_float4(0.f, 0.f, 0.f, 0.f);
            if (grow < NN) v = *(const float4*)(A + (size_t)grow * 64 + q * 4);
            float* dst = a_s + r * 65 + q * 4;
            dst[0] = v.x; dst[1] = v.y; dst[2] = v.z; dst[3] = v.w;
        }
        __syncthreads();
        const float* wm = w_s + m * 4096;
#pragma unroll 8
        for (int k = 0; k < 64; k++) {
            const float4 wv = *(const float4*)(wm + k * 64 + tc * 4);
#pragma unroll
            for (int i = 0; i < 8; i++) {
                float a = a_s[(tr * 8 + i) * 65 + k];
                acc[i][0] = fmaf(a, wv.x, acc[i][0]);
                acc[i][1] = fmaf(a, wv.y, acc[i][1]);
                acc[i][2] = fmaf(a, wv.z, acc[i][2]);
                acc[i][3] = fmaf(a, wv.w, acc[i][3]);
            }
        }
    }

    const float4 bv = *(const float4*)(bias + tc * 4);
    if (STATS) {
        if (tid < 128) st[tid] = 0.0f;
        __syncthreads();
    }
    float s0 = 0.f, s1 = 0.f, s2 = 0.f, s3 = 0.f;
    float q0 = 0.f, q1 = 0.f, q2 = 0.f, q3 = 0.f;
#pragma unroll
    for (int i = 0; i < 8; i++) {
        int grow = rowBase + tr * 8 + i;
        if (grow < NN) {
            float o0 = acc[i][0] + bv.x, o1 = acc[i][1] + bv.y;
            float o2 = acc[i][2] + bv.z, o3 = acc[i][3] + bv.w;
            *(float4*)(out + (size_t)grow * 64 + tc * 4) = make_float4(o0, o1, o2, o3);
            if (STATS) {
                s0 += o0; s1 += o1; s2 += o2; s3 += o3;
                q0 = fmaf(o0, o0, q0); q1 = fmaf(o1, o1, q1);
                q2 = fmaf(o2, o2, q2); q3 = fmaf(o3, o3, q3);
            }
        }
    }
    if (STATS) {
        atomicAdd(&st[tc * 4 + 0], s0); atomicAdd(&st[tc * 4 + 1], s1);
        atomicAdd(&st[tc * 4 + 2], s2); atomicAdd(&st[tc * 4 + 3], s3);
        atomicAdd(&st[64 + tc * 4 + 0], q0); atomicAdd(&st[64 + tc * 4 + 1], q1);
        atomicAdd(&st[64 + tc * 4 + 2], q2); atomicAdd(&st[64 + tc * 4 + 3], q3);
        __syncthreads();
        if (tid < 128) atomicAdd(&g_stats[tid], st[tid]);
    }
}

// ---------------- BN + leakyReLU (+ optional shortcut add) ----------------
__global__ void norm_kernel(const float* __restrict__ in, const float* __restrict__ gam,
                            const float* __restrict__ bet, const float* __restrict__ sc,
                            float* __restrict__ oh)
{
    int i = blockIdx.x * blockDim.x + threadIdx.x;
    if (i >= NN * 16) return;
    int c0 = (i & 15) * 4;
    float4 v = *(const float4*)(in + (size_t)i * 4);
    float4 s4 = make_float4(0.f, 0.f, 0.f, 0.f);
    if (sc) s4 = *(const float4*)(sc + (size_t)i * 4);
    float vv[4] = {v.x, v.y, v.z, v.w};
    float ss[4] = {s4.x, s4.y, s4.z, s4.w};
    float o[4];
    const float invN = 1.0f / (float)NN;
#pragma unroll
    for (int j = 0; j < 4; j++) {
        int c = c0 + j;
        float mu  = g_stats[c] * invN;
        float var = g_stats[64 + c] * invN - mu * mu;
        float isd = rsqrtf(var + 1e-5f);
        float y = (vv[j] - mu) * isd * gam[c] + bet[c];
        y = (y > 0.0f) ? y : 0.01f * y;
        o[j] = y + ss[j];
    }
    *(float4*)(oh + (size_t)i * 4) = make_float4(o[0], o[1], o[2], o[3]);
}

// ---------------- segment max pooling (batch is sorted) ----------------
__device__ __forceinline__ void atomicMaxFloat(float* addr, float v) {
    if (v >= 0.0f) atomicMax((int*)addr, __float_as_int(v));
    else           atomicMin((unsigned int*)addr, __float_as_uint(v));
}

__global__ void pool_kernel(const float* __restrict__ h, const void* __restrict__ batch) {
    int tid = blockIdx.x * blockDim.x + threadIdx.x;
    int c = tid & 63;
    int chunk = tid >> 6;
    if (chunk >= (NN + 63) / 64) return;
    int n0 = chunk * 64;
    int n1 = (n0 + 64 < NN) ? (n0 + 64) : NN;
    int curg = -1;
    float curm = 0.0f;
    for (int n = n0; n < n1; n++) {
        int g = load_idx(batch, n);
        if ((unsigned)g >= GG) continue;
        float v = h[(size_t)n * 64 + c];
        if (g != curg) {
            if (curg >= 0) atomicMaxFloat(&g_pool[curg * 64 + c], curm);
            curg = g;
            curm = v;
        } else {
            curm = fmaxf(curm, v);
        }
    }
    if (curg >= 0) atomicMaxFloat(&g_pool[curg * 64 + c], curm);
}

// ---------------- final GEMV [G,H]@[H,1] + b ----------------
__global__ void final_kernel(const float* __restrict__ wlin, const float* __restrict__ blin,
                             float* __restrict__ outp)
{
    int g = threadIdx.x;
    if (g < GG) {
        float s = blin[0];
#pragma unroll
        for (int k = 0; k < HH; k++) s = fmaf(g_pool[g * 64 + k], wlin[k], s);
        outp[g] = s;
    }
}

// ---------------- launch ----------------
extern "C" void kernel_launch(void* const* d_in, const int* in_sizes, int n_in,
                              void* d_out, int out_size)
{
    const float* x       = (const float*)d_in[0];
    const void*  ei      = d_in[1];
    const void*  bat     = d_in[2];
    const float* w1  = (const float*)d_in[3];
    const float* b1  = (const float*)d_in[4];
    const float* w2  = (const float*)d_in[5];
    const float* b2  = (const float*)d_in[6];
    const float* w3  = (const float*)d_in[7];
    const float* b3  = (const float*)d_in[8];
    const float* g1  = (const float*)d_in[9];
    const float* be1 = (const float*)d_in[10];
    const float* g2  = (const float*)d_in[11];
    const float* be2 = (const float*)d_in[12];
    const float* g3  = (const float*)d_in[13];
    const float* be3 = (const float*)d_in[14];
    const float* wsc = (const float*)d_in[15];
    const float* bsc = (const float*)d_in[16];
    const float* wl  = (const float*)d_in[17];
    const float* bl  = (const float*)d_in[18];
    float* outp = (float*)d_out;

    float *p_t1, *p_ts, *p_out, *p_h, *p_sc;
    cudaGetSymbolAddress((void**)&p_t1,  g_t1);
    cudaGetSymbolAddress((void**)&p_ts,  g_ts);
    cudaGetSymbolAddress((void**)&p_out, g_outb);
    cudaGetSymbolAddress((void**)&p_h,   g_h);
    cudaGetSymbolAddress((void**)&p_sc,  g_sc);

    const int smem3 = (3 * 4096 + 128 * 65 + 128) * (int)sizeof(float);
    const int smem1 = (1 * 4096 + 128 * 65 + 128) * (int)sizeof(float);
    cudaFuncSetAttribute(gemm_kernel<3, true>,  cudaFuncAttributeMaxDynamicSharedMemorySize, smem3);
    cudaFuncSetAttribute(gemm_kernel<1, false>, cudaFuncAttributeMaxDynamicSharedMemorySize, smem1);

    const int TB = 256;
    const int gridN  = (NN + TB - 1) / TB;
    const int gridE  = (EE + TB - 1) / TB;
    const int gridP  = (NN * 32 + TB - 1) / TB;       // warp per node
    const int gridG  = (NN + 127) / 128;              // gemm tiles
    const int gridNm = (NN * 16 + TB - 1) / TB;       // normalize (float4)
    const int gridPl = (((NN + 63) / 64) * 64 + TB - 1) / TB;

    // graph structure (recomputed every launch; deterministic work)
    init_kernel<<<gridN, TB>>>(ei);                    // 1 (detect + flag reset)
    hist_kernel<<<gridE, TB>>>(ei);                    // 2
    scan_kernel<<<SCAN_NB, 256>>>();                   // 3 (dis + cnt reset folded in)
    scatter_kernel<<<gridE, TB>>>(ei);                 // 4

    // layer 1 (input x)           -- launches 5,6 = prop (ncu -s 5 -c 1 -> prop)
    prop_kernel<<<gridP, TB>>>(x, p_t1);
    prop_kernel<<<gridP, TB>>>(p_t1, p_ts);
    gemm_kernel<3, true><<<gridG, TB, smem3>>>(x, p_t1, p_ts, w1, b1, p_out);
    norm_kernel<<<gridNm, TB>>>(p_out, g1, be1, nullptr, p_h);

    // layer 2
    prop_kernel<<<gridP, TB>>>(p_h, p_t1);
    prop_kernel<<<gridP, TB>>>(p_t1, p_ts);
    gemm_kernel<3, true><<<gridG, TB, smem3>>>(p_h, p_t1, p_ts, w2, b2, p_out);
    norm_kernel<<<gridNm, TB>>>(p_out, g2, be2, nullptr, p_h);

    // layer 3 (+ shortcut)
    prop_kernel<<<gridP, TB>>>(p_h, p_t1);
    prop_kernel<<<gridP, TB>>>(p_t1, p_ts);
    gemm_kernel<3, true><<<gridG, TB, smem3>>>(p_h, p_t1, p_ts, w3, b3, p_out);
    gemm_kernel<1, false><<<gridG, TB, smem1>>>(x, x, x, wsc, bsc, p_sc);
    norm_kernel<<<gridNm, TB>>>(p_out, g3, be3, p_sc, p_h);

    // pool + head
    pool_kernel<<<gridPl, TB>>>(p_h, bat);
    final_kernel<<<1, 64>>>(wl, bl, outp);
}

// round 12
// speedup vs baseline: 1.4402x; 1.0097x over previous
#include <cuda_runtime.h>
#include <cuda_fp16.h>
#include <cstdint>
#include <cfloat>

#define NN 100000
#define EE 1600000
#define GG 64
#define HH 64

#define SCAN_IT 16
#define SCAN_CHUNK 4096
#define SCAN_NB 25              // ceil(NN / SCAN_CHUNK)

// ---------------- scratch (static device globals; no allocation) ----------------
__device__ int    g_is64;                   // 1 if index inputs are int64, 0 if int32
__device__ int    g_cnt[NN];
__device__ float  g_dis[NN];
__device__ int    g_rowstart[NN + 1];
__device__ int    g_bsum[SCAN_NB];
__device__ int    g_bflag[SCAN_NB];
__device__ int2   g_csr[EE];                // {col, __float_as_int(norm)}
__device__ float  g_t1[(size_t)NN * 64];
__device__ float  g_ts[(size_t)NN * 64];
__device__ float  g_outb[(size_t)NN * 64];
__device__ float  g_h[(size_t)NN * 64];
__device__ float  g_sc[(size_t)NN * 64];
__device__ __half g_f16a[(size_t)NN * 64];  // fp16 mirror: x (L1) then h (L2/L3)
__device__ __half g_f16b[(size_t)NN * 64];  // fp16 mirror of Tx1
__device__ float  g_stats[128];             // [0:64) sum, [64:128) sumsq
__device__ float  g_pool[GG * HH];

__device__ __forceinline__ int load_idx(const void* p, size_t i) {
    return g_is64 ? (int)((const long long*)p)[i] : ((const int*)p)[i];
}

__device__ __forceinline__ uint2 pack_half4(float a, float b, float c, float d) {
    __half2 h0 = __floats2half2_rn(a, b);
    __half2 h1 = __floats2half2_rn(c, d);
    uint2 u;
    u.x = *(const unsigned*)&h0;
    u.y = *(const unsigned*)&h1;
    return u;
}

// ---------------- init (+ dtype detection folded in) ----------------
__global__ void init_kernel(const void* ei) {
    int i = blockIdx.x * blockDim.x + threadIdx.x;
    if (i == 0) {
        const long long* p = (const long long*)ei;
        int ok64 = 1;
        for (int e = 0; e < 256; e++) {
            long long v = p[e];
            if (v < 0 || v >= NN) { ok64 = 0; break; }
        }
        g_is64 = ok64;
    }
    if (i < NN) g_cnt[i] = 0;
    if (i < GG * HH) g_pool[i] = -FLT_MAX;
    if (i < SCAN_NB) g_bflag[i] = 0;
}

// ---------------- degree histogram (+ x -> fp16 mirror folded in) ----------------
__global__ void hist_kernel(const void* __restrict__ ei, const float* __restrict__ x) {
    int e = blockIdx.x * blockDim.x + threadIdx.x;
    if (e < EE) {
        int r = load_idx(ei, e);
        if ((unsigned)r < NN) atomicAdd(&g_cnt[r], 1);
    }
    if (e < NN * 16) {                       // NN*16 == 1.6M == EE
        float4 v = *(const float4*)(x + (size_t)e * 4);
        ((uint2*)g_f16a)[e] = pack_half4(v.x, v.y, v.z, v.w);
    }
}

// ---------------- parallel scan: g_cnt -> g_rowstart (exclusive) ----------------
__device__ __forceinline__ int warp_scan_incl(int v, int lane) {
#pragma unroll
    for (int o = 1; o < 32; o <<= 1) {
        int t = __shfl_up_sync(0xffffffffu, v, o);
        if (lane >= o) v += t;
    }
    return v;
}

__global__ void __launch_bounds__(256) scan_kernel() {
    __shared__ int wtot[8];
    __shared__ int s_prefix;
    const int bid = blockIdx.x, tid = threadIdx.x;
    const int lane = tid & 31, wid = tid >> 5;
    const int base = bid * SCAN_CHUNK + tid * SCAN_IT;

    int v[SCAN_IT];
    int tsum = 0;
#pragma unroll
    for (int i = 0; i < SCAN_IT; i++) {
        int idx = base + i;
        int val = 0;
        if (idx < NN) {
            val = g_cnt[idx];
            g_cnt[idx] = 0;
            g_dis[idx] = (val > 0) ? rsqrtf((float)val) : 0.0f;
        }
        v[i] = tsum;            // exclusive within thread
        tsum += val;
    }
    int incl = warp_scan_incl(tsum, lane);
    if (lane == 31) wtot[wid] = incl;
    __syncthreads();
    if (wid == 0) {
        int s = (lane < 8) ? wtot[lane] : 0;
        int si = warp_scan_incl(s, lane);
        if (lane < 8) wtot[lane] = si;
    }
    __syncthreads();
    int warpExcl = wid ? wtot[wid - 1] : 0;
    int threadExcl = warpExcl + incl - tsum;
    int blockTot = wtot[7];

    if (tid == 0) {
        int prefix = 0;
        if (bid > 0) {
            while (atomicAdd(&g_bflag[bid - 1], 0) == 0) { }
            prefix = g_bsum[bid - 1];
        }
        g_bsum[bid] = prefix + blockTot;
        __threadfence();
        atomicExch(&g_bflag[bid], 1);
        s_prefix = prefix;
        if (bid == SCAN_NB - 1) g_rowstart[NN] = prefix + blockTot;  // == EE
    }
    __syncthreads();
    int pref = s_prefix + threadExcl;
#pragma unroll
    for (int i = 0; i < SCAN_IT; i++) {
        int idx = base + i;
        if (idx < NN) g_rowstart[idx] = pref + v[i];
    }
}

// ---------------- scatter edges into CSR (with norm) ----------------
__global__ void scatter_kernel(const void* __restrict__ ei) {
    int e = blockIdx.x * blockDim.x + threadIdx.x;
    if (e >= EE) return;
    int r = load_idx(ei, e);
    int c = load_idx(ei, (size_t)EE + e);
    if ((unsigned)r >= NN || (unsigned)c >= NN) return;
    int pos = g_rowstart[r] + atomicAdd(&g_cnt[r], 1);
    if ((unsigned)pos >= EE) return;
    float nm = -g_dis[r] * g_dis[c];
    g_csr[pos] = make_int2(c, __float_as_int(nm));
}

// ---------------- propagation: out[r] = sum_e norm * in16[col_e]  (fp16 gather) ----------------
// Warp per node; two 16-lane halves each cover the full 64-elem row (uint2 = 4
// halves per lane); half 0 even edges, half 1 odd edges; unroll x2 -> 4
// independent 8B gathers in flight. fp32 accumulate. Optional fp16 echo of the
// output for the next prop's gather. Also zeroes g_stats for the BN pass.
template <bool OUT16>
__global__ void prop_kernel(const __half* __restrict__ in, float* __restrict__ out,
                            __half* __restrict__ out16)
{
    if (blockIdx.x == 0 && threadIdx.x < 128) g_stats[threadIdx.x] = 0.0f;
    int w = (blockIdx.x * blockDim.x + threadIdx.x) >> 5;
    if (w >= NN) return;
    int lane = threadIdx.x & 31;
    int sub = lane >> 4;             // which half
    int lc  = lane & 15;             // 4-elem group within row
    int s = g_rowstart[w];
    int e = g_rowstart[w + 1];
    float4 a0 = make_float4(0.f, 0.f, 0.f, 0.f);
    float4 a1 = make_float4(0.f, 0.f, 0.f, 0.f);
    int j = s + sub;
    for (; j + 2 < e; j += 4) {
        int2 r0 = g_csr[j];
        int2 r1 = g_csr[j + 2];
        uint2 u0 = ((const uint2*)(in + (size_t)r0.x * 64))[lc];
        uint2 u1 = ((const uint2*)(in + (size_t)r1.x * 64))[lc];
        float n0 = __int_as_float(r0.y), n1 = __int_as_float(r1.y);
        float2 p00 = __half22float2(*(const __half2*)&u0.x);
        float2 p01 = __half22float2(*(const __half2*)&u0.y);
        float2 p10 = __half22float2(*(const __half2*)&u1.x);
        float2 p11 = __half22float2(*(const __half2*)&u1.y);
        a0.x = fmaf(n0, p00.x, a0.x); a0.y = fmaf(n0, p00.y, a0.y);
        a0.z = fmaf(n0, p01.x, a0.z); a0.w = fmaf(n0, p01.y, a0.w);
        a1.x = fmaf(n1, p10.x, a1.x); a1.y = fmaf(n1, p10.y, a1.y);
        a1.z = fmaf(n1, p11.x, a1.z); a1.w = fmaf(n1, p11.y, a1.w);
    }
    if (j < e) {
        int2 r0 = g_csr[j];
        uint2 u0 = ((const uint2*)(in + (size_t)r0.x * 64))[lc];
        float n0 = __int_as_float(r0.y);
        float2 p00 = __half22float2(*(const __half2*)&u0.x);
        float2 p01 = __half22float2(*(const __half2*)&u0.y);
        a0.x = fmaf(n0, p00.x, a0.x); a0.y = fmaf(n0, p00.y, a0.y);
        a0.z = fmaf(n0, p01.x, a0.z); a0.w = fmaf(n0, p01.y, a0.w);
    }
    a0.x += a1.x; a0.y += a1.y; a0.z += a1.z; a0.w += a1.w;
    a0.x += __shfl_down_sync(0xffffffffu, a0.x, 16);
    a0.y += __shfl_down_sync(0xffffffffu, a0.y, 16);
    a0.z += __shfl_down_sync(0xffffffffu, a0.z, 16);
    a0.w += __shfl_down_sync(0xffffffffu, a0.w, 16);
    if (sub == 0) {
        *(float4*)(out + (size_t)w * 64 + lc * 4) = a0;
        if (OUT16)
            ((uint2*)(out16 + (size_t)w * 64))[lc] = pack_half4(a0.x, a0.y, a0.z, a0.w);
    }
}

// ---------------- fused GEMM:
// NM==3: out = A0@(W0-W2) + A1@W1 + A2@(2*W2) + bias   (ChebConv, Tx2 folded in)
// NM==1: out = A0@W + bias                              (shortcut)
// STATS: accumulate per-channel sum/sumsq into g_stats
template <int NM, bool STATS>
__global__ void __launch_bounds__(256) gemm_kernel(
    const float* __restrict__ A0, const float* __restrict__ A1, const float* __restrict__ A2,
    const float* __restrict__ W, const float* __restrict__ bias, float* __restrict__ out)
{
    extern __shared__ float sm[];
    float* w_s = sm;                       // NM*64*64
    float* a_s = sm + NM * 4096;           // 128*65
    float* st  = a_s + 128 * 65;           // 128
    const int tid = threadIdx.x;
    const int tc = tid & 15;               // column group (4 cols)
    const int tr = tid >> 4;               // row group (8 rows)
    const int rowBase = blockIdx.x * 128;

    for (int idx = tid; idx < NM * 4096; idx += 256) {
        float v;
        if (NM == 3) {
            int m = idx >> 12, r = idx & 4095;
            if (m == 0)      v = W[r] - W[8192 + r];
            else if (m == 1) v = W[4096 + r];
            else             v = 2.0f * W[8192 + r];
        } else {
            v = W[idx];
        }
        w_s[idx] = v;
    }

    float acc[8][4];
#pragma unroll
    for (int i = 0; i < 8; i++) {
        acc[i][0] = 0.f; acc[i][1] = 0.f; acc[i][2] = 0.f; acc[i][3] = 0.f;
    }

    const float* As[3] = {A0, A1, A2};
#pragma unroll
    for (int m = 0; m < NM; m++) {
        __syncthreads();
        const float* __restrict__ A = As[m];
        for (int idx = tid; idx < 2048; idx += 256) {
            int r = idx >> 4, q = idx & 15;
            int grow = rowBase + r;
            float4 v = make_float4(0.f, 0.f, 0.f, 0.f);
            if (grow < NN) v = *(const float4*)(A + (size_t)grow * 64 + q * 4);
            float* dst = a_s + r * 65 + q * 4;
            dst[0] = v.x; dst[1] = v.y; dst[2] = v.z; dst[3] = v.w;
        }
        __syncthreads();
        const float* wm = w_s + m * 4096;
#pragma unroll 8
        for (int k = 0; k < 64; k++) {
            const float4 wv = *(const float4*)(wm + k * 64 + tc * 4);
#pragma unroll
            for (int i = 0; i < 8; i++) {
                float a = a_s[(tr * 8 + i) * 65 + k];
                acc[i][0] = fmaf(a, wv.x, acc[i][0]);
                acc[i][1] = fmaf(a, wv.y, acc[i][1]);
                acc[i][2] = fmaf(a, wv.z, acc[i][2]);
                acc[i][3] = fmaf(a, wv.w, acc[i][3]);
            }
        }
    }

    const float4 bv = *(const float4*)(bias + tc * 4);
    if (STATS) {
        if (tid < 128) st[tid] = 0.0f;
        __syncthreads();
    }
    float s0 = 0.f, s1 = 0.f, s2 = 0.f, s3 = 0.f;
    float q0 = 0.f, q1 = 0.f, q2 = 0.f, q3 = 0.f;
#pragma unroll
    for (int i = 0; i < 8; i++) {
        int grow = rowBase + tr * 8 + i;
        if (grow < NN) {
            float o0 = acc[i][0] + bv.x, o1 = acc[i][1] + bv.y;
            float o2 = acc[i][2] + bv.z, o3 = acc[i][3] + bv.w;
            *(float4*)(out + (size_t)grow * 64 + tc * 4) = make_float4(o0, o1, o2, o3);
            if (STATS) {
                s0 += o0; s1 += o1; s2 += o2; s3 += o3;
                q0 = fmaf(o0, o0, q0); q1 = fmaf(o1, o1, q1);
                q2 = fmaf(o2, o2, q2); q3 = fmaf(o3, o3, q3);
            }
        }
    }
    if (STATS) {
        atomicAdd(&st[tc * 4 + 0], s0); atomicAdd(&st[tc * 4 + 1], s1);
        atomicAdd(&st[tc * 4 + 2], s2); atomicAdd(&st[tc * 4 + 3], s3);
        atomicAdd(&st[64 + tc * 4 + 0], q0); atomicAdd(&st[64 + tc * 4 + 1], q1);
        atomicAdd(&st[64 + tc * 4 + 2], q2); atomicAdd(&st[64 + tc * 4 + 3], q3);
        __syncthreads();
        if (tid < 128) atomicAdd(&g_stats[tid], st[tid]);
    }
}

// ---------------- BN + leakyReLU (+ optional shortcut add, + optional fp16 echo) ----------------
__global__ void norm_kernel(const float* __restrict__ in, const float* __restrict__ gam,
                            const float* __restrict__ bet, const float* __restrict__ sc,
                            float* __restrict__ oh, __half* __restrict__ oh16)
{
    int i = blockIdx.x * blockDim.x + threadIdx.x;
    if (i >= NN * 16) return;
    int c0 = (i & 15) * 4;
    float4 v = *(const float4*)(in + (size_t)i * 4);
    float4 s4 = make_float4(0.f, 0.f, 0.f, 0.f);
    if (sc) s4 = *(const float4*)(sc + (size_t)i * 4);
    float vv[4] = {v.x, v.y, v.z, v.w};
    float ss[4] = {s4.x, s4.y, s4.z, s4.w};
    float o[4];
    const float invN = 1.0f / (float)NN;
#pragma unroll
    for (int j = 0; j < 4; j++) {
        int c = c0 + j;
        float mu  = g_stats[c] * invN;
        float var = g_stats[64 + c] * invN - mu * mu;
        float isd = rsqrtf(var + 1e-5f);
        float y = (vv[j] - mu) * isd * gam[c] + bet[c];
        y = (y > 0.0f) ? y : 0.01f * y;
        o[j] = y + ss[j];
    }
    *(float4*)(oh + (size_t)i * 4) = make_float4(o[0], o[1], o[2], o[3]);
    if (oh16)
        ((uint2*)oh16)[i] = pack_half4(o[0], o[1], o[2], o[3]);
}

// ---------------- segment max pooling (batch is sorted) ----------------
__device__ __forceinline__ void atomicMaxFloat(float* addr, float v) {
    if (v >= 0.0f) atomicMax((int*)addr, __float_as_int(v));
    else           atomicMin((unsigned int*)addr, __float_as_uint(v));
}

__global__ void pool_kernel(const float* __restrict__ h, const void* __restrict__ batch) {
    int tid = blockIdx.x * blockDim.x + threadIdx.x;
    int c = tid & 63;
    int chunk = tid >> 6;
    if (chunk >= (NN + 63) / 64) return;
    int n0 = chunk * 64;
    int n1 = (n0 + 64 < NN) ? (n0 + 64) : NN;
    int curg = -1;
    float curm = 0.0f;
    for (int n = n0; n < n1; n++) {
        int g = load_idx(batch, n);
        if ((unsigned)g >= GG) continue;
        float v = h[(size_t)n * 64 + c];
        if (g != curg) {
            if (curg >= 0) atomicMaxFloat(&g_pool[curg * 64 + c], curm);
            curg = g;
            curm = v;
        } else {
            curm = fmaxf(curm, v);
        }
    }
    if (curg >= 0) atomicMaxFloat(&g_pool[curg * 64 + c], curm);
}

// ---------------- final GEMV [G,H]@[H,1] + b ----------------
__global__ void final_kernel(const float* __restrict__ wlin, const float* __restrict__ blin,
                             float* __restrict__ outp)
{
    int g = threadIdx.x;
    if (g < GG) {
        float s = blin[0];
#pragma unroll
        for (int k = 0; k < HH; k++) s = fmaf(g_pool[g * 64 + k], wlin[k], s);
        outp[g] = s;
    }
}

// ---------------- launch ----------------
extern "C" void kernel_launch(void* const* d_in, const int* in_sizes, int n_in,
                              void* d_out, int out_size)
{
    const float* x       = (const float*)d_in[0];
    const void*  ei      = d_in[1];
    const void*  bat     = d_in[2];
    const float* w1  = (const float*)d_in[3];
    const float* b1  = (const float*)d_in[4];
    const float* w2  = (const float*)d_in[5];
    const float* b2  = (const float*)d_in[6];
    const float* w3  = (const float*)d_in[7];
    const float* b3  = (const float*)d_in[8];
    const float* g1  = (const float*)d_in[9];
    const float* be1 = (const float*)d_in[10];
    const float* g2  = (const float*)d_in[11];
    const float* be2 = (const float*)d_in[12];
    const float* g3  = (const float*)d_in[13];
    const float* be3 = (const float*)d_in[14];
    const float* wsc = (const float*)d_in[15];
    const float* bsc = (const float*)d_in[16];
    const float* wl  = (const float*)d_in[17];
    const float* bl  = (const float*)d_in[18];
    float* outp = (float*)d_out;

    float *p_t1, *p_ts, *p_out, *p_h, *p_sc;
    __half *p_a16, *p_b16;
    cudaGetSymbolAddress((void**)&p_t1,  g_t1);
    cudaGetSymbolAddress((void**)&p_ts,  g_ts);
    cudaGetSymbolAddress((void**)&p_out, g_outb);
    cudaGetSymbolAddress((void**)&p_h,   g_h);
    cudaGetSymbolAddress((void**)&p_sc,  g_sc);
    cudaGetSymbolAddress((void**)&p_a16, g_f16a);
    cudaGetSymbolAddress((void**)&p_b16, g_f16b);

    const int smem3 = (3 * 4096 + 128 * 65 + 128) * (int)sizeof(float);
    const int smem1 = (1 * 4096 + 128 * 65 + 128) * (int)sizeof(float);
    cudaFuncSetAttribute(gemm_kernel<3, true>,  cudaFuncAttributeMaxDynamicSharedMemorySize, smem3);
    cudaFuncSetAttribute(gemm_kernel<1, false>, cudaFuncAttributeMaxDynamicSharedMemorySize, smem1);

    const int TB = 256;
    const int gridN  = (NN + TB - 1) / TB;
    const int gridE  = (EE + TB - 1) / TB;
    const int gridP  = (NN * 32 + TB - 1) / TB;       // warp per node
    const int gridG  = (NN + 127) / 128;              // gemm tiles
    const int gridNm = (NN * 16 + TB - 1) / TB;       // normalize (float4)
    const int gridPl = (((NN + 63) / 64) * 64 + TB - 1) / TB;

    // graph structure (recomputed every launch; deterministic work)
    init_kernel<<<gridN, TB>>>(ei);                    // 1 (detect + flag reset)
    hist_kernel<<<gridE, TB>>>(ei, x);                 // 2 (+ x -> fp16 mirror)
    scan_kernel<<<SCAN_NB, 256>>>();                   // 3 (dis + cnt reset folded in)
    scatter_kernel<<<gridE, TB>>>(ei);                 // 4

    // layer 1 (input x; fp16 mirror in p_a16)
    prop_kernel<true ><<<gridP, TB>>>(p_a16, p_t1, p_b16);
    prop_kernel<false><<<gridP, TB>>>(p_b16, p_ts, nullptr);
    gemm_kernel<3, true><<<gridG, TB, smem3>>>(x, p_t1, p_ts, w1, b1, p_out);
    norm_kernel<<<gridNm, TB>>>(p_out, g1, be1, nullptr, p_h, p_a16);

    // layer 2
    prop_kernel<true ><<<gridP, TB>>>(p_a16, p_t1, p_b16);
    prop_kernel<false><<<gridP, TB>>>(p_b16, p_ts, nullptr);
    gemm_kernel<3, true><<<gridG, TB, smem3>>>(p_h, p_t1, p_ts, w2, b2, p_out);
    norm_kernel<<<gridNm, TB>>>(p_out, g2, be2, nullptr, p_h, p_a16);

    // layer 3 (+ shortcut)
    prop_kernel<true ><<<gridP, TB>>>(p_a16, p_t1, p_b16);
    prop_kernel<false><<<gridP, TB>>>(p_b16, p_ts, nullptr);
    gemm_kernel<3, true><<<gridG, TB, smem3>>>(p_h, p_t1, p_ts, w3, b3, p_out);
    gemm_kernel<1, false><<<gridG, TB, smem1>>>(x, x, x, wsc, bsc, p_sc);
    norm_kernel<<<gridNm, TB>>>(p_out, g3, be3, p_sc, p_h, nullptr);

    // pool + head
    pool_kernel<<<gridPl, TB>>>(p_h, bat);
    final_kernel<<<1, 64>>>(wl, bl, outp);
}

// round 13
// speedup vs baseline: 1.5638x; 1.0859x over previous
#include <cuda_runtime.h>
#include <cuda_fp16.h>
#include <cstdint>
#include <cfloat>

#define NN 100000
#define EE 1600000
#define GG 64
#define HH 64

#define SCAN_IT 16
#define SCAN_CHUNK 4096
#define SCAN_NB 25              // ceil(NN / SCAN_CHUNK)

// ---------------- scratch (static device globals; no allocation) ----------------
__device__ int    g_is64;                   // 1 if index inputs are int64, 0 if int32
__device__ int    g_cnt[NN];
__device__ float  g_dis[NN];
__device__ int    g_rowstart[NN + 1];
__device__ int    g_bsum[SCAN_NB];
__device__ int    g_bflag[SCAN_NB];
__device__ int2   g_csr[EE];                // {col, __float_as_int(norm)}
__device__ float  g_t1[(size_t)NN * 64];
__device__ float  g_ts[(size_t)NN * 64];
__device__ float  g_outb[(size_t)NN * 64];
__device__ float  g_h[(size_t)NN * 64];
__device__ float  g_sc[(size_t)NN * 64];
__device__ __half g_f16a[(size_t)NN * 64];  // fp16 mirror: x (L1) then h (L2/L3)
__device__ __half g_f16b[(size_t)NN * 64];  // fp16 mirror of Tx1
__device__ float  g_stats[128];             // [0:64) sum, [64:128) sumsq
__device__ float  g_pool[GG * HH];

__device__ __forceinline__ int load_idx(const void* p, size_t i) {
    return g_is64 ? (int)((const long long*)p)[i] : ((const int*)p)[i];
}

__device__ __forceinline__ uint2 pack_half4(float a, float b, float c, float d) {
    __half2 h0 = __floats2half2_rn(a, b);
    __half2 h1 = __floats2half2_rn(c, d);
    uint2 u;
    u.x = *(const unsigned*)&h0;
    u.y = *(const unsigned*)&h1;
    return u;
}

__device__ __forceinline__ unsigned f2tf32(float v) {
    unsigned t;
    asm("cvt.rna.tf32.f32 %0, %1;" : "=r"(t) : "f"(v));
    return t;
}

// ---------------- init (+ dtype detection folded in) ----------------
__global__ void init_kernel(const void* ei) {
    int i = blockIdx.x * blockDim.x + threadIdx.x;
    if (i == 0) {
        const long long* p = (const long long*)ei;
        int ok64 = 1;
        for (int e = 0; e < 256; e++) {
            long long v = p[e];
            if (v < 0 || v >= NN) { ok64 = 0; break; }
        }
        g_is64 = ok64;
    }
    if (i < NN) g_cnt[i] = 0;
    if (i < GG * HH) g_pool[i] = -FLT_MAX;
    if (i < SCAN_NB) g_bflag[i] = 0;
}

// ---------------- degree histogram (+ x -> fp16 mirror folded in) ----------------
__global__ void hist_kernel(const void* __restrict__ ei, const float* __restrict__ x) {
    int e = blockIdx.x * blockDim.x + threadIdx.x;
    if (e < EE) {
        int r = load_idx(ei, e);
        if ((unsigned)r < NN) atomicAdd(&g_cnt[r], 1);
    }
    if (e < NN * 16) {                       // NN*16 == 1.6M == EE
        float4 v = *(const float4*)(x + (size_t)e * 4);
        ((uint2*)g_f16a)[e] = pack_half4(v.x, v.y, v.z, v.w);
    }
}

// ---------------- parallel scan: g_cnt -> g_rowstart (exclusive) ----------------
__device__ __forceinline__ int warp_scan_incl(int v, int lane) {
#pragma unroll
    for (int o = 1; o < 32; o <<= 1) {
        int t = __shfl_up_sync(0xffffffffu, v, o);
        if (lane >= o) v += t;
    }
    return v;
}

__global__ void __launch_bounds__(256) scan_kernel() {
    __shared__ int wtot[8];
    __shared__ int s_prefix;
    const int bid = blockIdx.x, tid = threadIdx.x;
    const int lane = tid & 31, wid = tid >> 5;
    const int base = bid * SCAN_CHUNK + tid * SCAN_IT;

    int v[SCAN_IT];
    int tsum = 0;
#pragma unroll
    for (int i = 0; i < SCAN_IT; i++) {
        int idx = base + i;
        int val = 0;
        if (idx < NN) {
            val = g_cnt[idx];
            g_cnt[idx] = 0;
            g_dis[idx] = (val > 0) ? rsqrtf((float)val) : 0.0f;
        }
        v[i] = tsum;            // exclusive within thread
        tsum += val;
    }
    int incl = warp_scan_incl(tsum, lane);
    if (lane == 31) wtot[wid] = incl;
    __syncthreads();
    if (wid == 0) {
        int s = (lane < 8) ? wtot[lane] : 0;
        int si = warp_scan_incl(s, lane);
        if (lane < 8) wtot[lane] = si;
    }
    __syncthreads();
    int warpExcl = wid ? wtot[wid - 1] : 0;
    int threadExcl = warpExcl + incl - tsum;
    int blockTot = wtot[7];

    if (tid == 0) {
        int prefix = 0;
        if (bid > 0) {
            while (atomicAdd(&g_bflag[bid - 1], 0) == 0) { }
            prefix = g_bsum[bid - 1];
        }
        g_bsum[bid] = prefix + blockTot;
        __threadfence();
        atomicExch(&g_bflag[bid], 1);
        s_prefix = prefix;
        if (bid == SCAN_NB - 1) g_rowstart[NN] = prefix + blockTot;  // == EE
    }
    __syncthreads();
    int pref = s_prefix + threadExcl;
#pragma unroll
    for (int i = 0; i < SCAN_IT; i++) {
        int idx = base + i;
        if (idx < NN) g_rowstart[idx] = pref + v[i];
    }
}

// ---------------- scatter edges into CSR (with norm) ----------------
__global__ void scatter_kernel(const void* __restrict__ ei) {
    int e = blockIdx.x * blockDim.x + threadIdx.x;
    if (e >= EE) return;
    int r = load_idx(ei, e);
    int c = load_idx(ei, (size_t)EE + e);
    if ((unsigned)r >= NN || (unsigned)c >= NN) return;
    int pos = g_rowstart[r] + atomicAdd(&g_cnt[r], 1);
    if ((unsigned)pos >= EE) return;
    float nm = -g_dis[r] * g_dis[c];
    g_csr[pos] = make_int2(c, __float_as_int(nm));
}

// ---------------- propagation: out[r] = sum_e norm * in16[col_e]  (fp16 gather) ----------------
template <bool OUT16>
__global__ void prop_kernel(const __half* __restrict__ in, float* __restrict__ out,
                            __half* __restrict__ out16)
{
    if (blockIdx.x == 0 && threadIdx.x < 128) g_stats[threadIdx.x] = 0.0f;
    int w = (blockIdx.x * blockDim.x + threadIdx.x) >> 5;
    if (w >= NN) return;
    int lane = threadIdx.x & 31;
    int sub = lane >> 4;             // which half
    int lc  = lane & 15;             // 4-elem group within row
    int s = g_rowstart[w];
    int e = g_rowstart[w + 1];
    float4 a0 = make_float4(0.f, 0.f, 0.f, 0.f);
    float4 a1 = make_float4(0.f, 0.f, 0.f, 0.f);
    int j = s + sub;
    for (; j + 2 < e; j += 4) {
        int2 r0 = g_csr[j];
        int2 r1 = g_csr[j + 2];
        uint2 u0 = ((const uint2*)(in + (size_t)r0.x * 64))[lc];
        uint2 u1 = ((const uint2*)(in + (size_t)r1.x * 64))[lc];
        float n0 = __int_as_float(r0.y), n1 = __int_as_float(r1.y);
        float2 p00 = __half22float2(*(const __half2*)&u0.x);
        float2 p01 = __half22float2(*(const __half2*)&u0.y);
        float2 p10 = __half22float2(*(const __half2*)&u1.x);
        float2 p11 = __half22float2(*(const __half2*)&u1.y);
        a0.x = fmaf(n0, p00.x, a0.x); a0.y = fmaf(n0, p00.y, a0.y);
        a0.z = fmaf(n0, p01.x, a0.z); a0.w = fmaf(n0, p01.y, a0.w);
        a1.x = fmaf(n1, p10.x, a1.x); a1.y = fmaf(n1, p10.y, a1.y);
        a1.z = fmaf(n1, p11.x, a1.z); a1.w = fmaf(n1, p11.y, a1.w);
    }
    if (j < e) {
        int2 r0 = g_csr[j];
        uint2 u0 = ((const uint2*)(in + (size_t)r0.x * 64))[lc];
        float n0 = __int_as_float(r0.y);
        float2 p00 = __half22float2(*(const __half2*)&u0.x);
        float2 p01 = __half22float2(*(const __half2*)&u0.y);
        a0.x = fmaf(n0, p00.x, a0.x); a0.y = fmaf(n0, p00.y, a0.y);
        a0.z = fmaf(n0, p01.x, a0.z); a0.w = fmaf(n0, p01.y, a0.w);
    }
    a0.x += a1.x; a0.y += a1.y; a0.z += a1.z; a0.w += a1.w;
    a0.x += __shfl_down_sync(0xffffffffu, a0.x, 16);
    a0.y += __shfl_down_sync(0xffffffffu, a0.y, 16);
    a0.z += __shfl_down_sync(0xffffffffu, a0.z, 16);
    a0.w += __shfl_down_sync(0xffffffffu, a0.w, 16);
    if (sub == 0) {
        *(float4*)(out + (size_t)w * 64 + lc * 4) = a0;
        if (OUT16)
            ((uint2*)(out16 + (size_t)w * 64))[lc] = pack_half4(a0.x, a0.y, a0.z, a0.w);
    }
}

// ---------------- fused tf32 tensor-core GEMM:
// NM==3: out = A0@(W0-W2) + A1@W1 + A2@(2*W2) + bias   (ChebConv, Tx2 folded in)
// NM==1: out = A0@W + bias                              (shortcut)
// Block: 256 thr = 8 warps; tile 128 rows x 64 cols; warp = 16 rows x 64 cols.
// mma.sync.m16n8k8 tf32, fp32 accumulate. STATS: per-channel sum/sumsq -> g_stats.
template <int NM, bool STATS>
__global__ void __launch_bounds__(256) gemm_kernel(
    const float* __restrict__ A0, const float* __restrict__ A1, const float* __restrict__ A2,
    const float* __restrict__ W, const float* __restrict__ bias, float* __restrict__ out)
{
    extern __shared__ float sm[];
    float* w_s = sm;                         // NM * 64 * 72 (tf32 bits), pitch 72
    float* a_s = sm + NM * 4608;             // 128 * 68 (tf32 bits), pitch 68
    float* st  = a_s + 128 * 68;             // 128 stats
    const int tid  = threadIdx.x;
    const int warp = tid >> 5, lane = tid & 31;
    const int gid  = lane >> 2;              // groupID  0..7
    const int tig  = lane & 3;               // thread-in-group 0..3
    const int rowBase = blockIdx.x * 128;

    // stage W (fold Cheb, convert tf32)
    for (int idx = tid; idx < NM * 4096; idx += 256) {
        float v;
        int m = idx >> 12, r = idx & 4095;   // r = k*64 + col
        if (NM == 3) {
            if (m == 0)      v = W[r] - W[8192 + r];
            else if (m == 1) v = W[4096 + r];
            else             v = 2.0f * W[8192 + r];
        } else {
            v = W[idx];
        }
        int k = r >> 6, col = r & 63;
        ((unsigned*)w_s)[m * 4608 + k * 72 + col] = f2tf32(v);
    }

    float c[8][4];
#pragma unroll
    for (int nt = 0; nt < 8; nt++) {
        c[nt][0] = 0.f; c[nt][1] = 0.f; c[nt][2] = 0.f; c[nt][3] = 0.f;
    }

    const float* As[3] = {A0, A1, A2};
#pragma unroll
    for (int m = 0; m < NM; m++) {
        __syncthreads();
        const float* __restrict__ A = As[m];
        for (int idx = tid; idx < 2048; idx += 256) {
            int r = idx >> 4, q = idx & 15;
            int grow = rowBase + r;
            float4 v = make_float4(0.f, 0.f, 0.f, 0.f);
            if (grow < NN) v = *(const float4*)(A + (size_t)grow * 64 + q * 4);
            unsigned* dst = (unsigned*)a_s + r * 68 + q * 4;
            dst[0] = f2tf32(v.x); dst[1] = f2tf32(v.y);
            dst[2] = f2tf32(v.z); dst[3] = f2tf32(v.w);
        }
        __syncthreads();
        const unsigned* wm  = (const unsigned*)w_s + m * 4608;
        const unsigned* ar0 = (const unsigned*)a_s + (warp * 16 + gid) * 68;
        const unsigned* ar1 = ar0 + 8 * 68;
#pragma unroll
        for (int ks = 0; ks < 8; ks++) {
            int k0 = ks * 8;
            unsigned fa0 = ar0[k0 + tig];
            unsigned fa1 = ar1[k0 + tig];
            unsigned fa2 = ar0[k0 + tig + 4];
            unsigned fa3 = ar1[k0 + tig + 4];
            const unsigned* bp0 = wm + (k0 + tig) * 72 + gid;
            const unsigned* bp1 = bp0 + 4 * 72;
#pragma unroll
            for (int nt = 0; nt < 8; nt++) {
                unsigned fb0 = bp0[nt * 8];
                unsigned fb1 = bp1[nt * 8];
                asm volatile(
                    "mma.sync.aligned.m16n8k8.row.col.f32.tf32.tf32.f32 "
                    "{%0,%1,%2,%3}, {%4,%5,%6,%7}, {%8,%9}, {%0,%1,%2,%3};"
                    : "+f"(c[nt][0]), "+f"(c[nt][1]), "+f"(c[nt][2]), "+f"(c[nt][3])
                    : "r"(fa0), "r"(fa1), "r"(fa2), "r"(fa3), "r"(fb0), "r"(fb1));
            }
        }
    }

    // epilogue: bias add, store, BN stats
    if (STATS) {
        __syncthreads();
        if (tid < 128) st[tid] = 0.0f;
        __syncthreads();
    }
    const int grow0 = rowBase + warp * 16 + gid;
    const int grow1 = grow0 + 8;
    const bool v0 = grow0 < NN, v1 = grow1 < NN;
    float ssum[16], ssq[16];
#pragma unroll
    for (int nt = 0; nt < 8; nt++) {
        int col = nt * 8 + tig * 2;
        float bv0 = bias[col], bv1 = bias[col + 1];
        float o00 = c[nt][0] + bv0, o01 = c[nt][1] + bv1;
        float o10 = c[nt][2] + bv0, o11 = c[nt][3] + bv1;
        if (v0) *(float2*)(out + (size_t)grow0 * 64 + col) = make_float2(o00, o01);
        if (v1) *(float2*)(out + (size_t)grow1 * 64 + col) = make_float2(o10, o11);
        if (STATS) {
            ssum[nt * 2]     = (v0 ? o00 : 0.f) + (v1 ? o10 : 0.f);
            ssum[nt * 2 + 1] = (v0 ? o01 : 0.f) + (v1 ? o11 : 0.f);
            ssq[nt * 2]      = (v0 ? o00 * o00 : 0.f) + (v1 ? o10 * o10 : 0.f);
            ssq[nt * 2 + 1]  = (v0 ? o01 * o01 : 0.f) + (v1 ? o11 * o11 : 0.f);
        }
    }
    if (STATS) {
        // reduce over the 8 lanes sharing the same tig (stride-4 lanes)
#pragma unroll
        for (int i = 0; i < 16; i++) {
            float s = ssum[i], q = ssq[i];
            s += __shfl_down_sync(0xffffffffu, s, 16);
            s += __shfl_down_sync(0xffffffffu, s, 8);
            s += __shfl_down_sync(0xffffffffu, s, 4);
            q += __shfl_down_sync(0xffffffffu, q, 16);
            q += __shfl_down_sync(0xffffffffu, q, 8);
            q += __shfl_down_sync(0xffffffffu, q, 4);
            if (lane < 4) {
                int col = (i >> 1) * 8 + lane * 2 + (i & 1);
                atomicAdd(&st[col], s);
                atomicAdd(&st[64 + col], q);
            }
        }
        __syncthreads();
        if (tid < 128) atomicAdd(&g_stats[tid], st[tid]);
    }
}

// ---------------- BN + leakyReLU (+ optional shortcut add, + optional fp16 echo) ----------------
__global__ void norm_kernel(const float* __restrict__ in, const float* __restrict__ gam,
                            const float* __restrict__ bet, const float* __restrict__ sc,
                            float* __restrict__ oh, __half* __restrict__ oh16)
{
    int i = blockIdx.x * blockDim.x + threadIdx.x;
    if (i >= NN * 16) return;
    int c0 = (i & 15) * 4;
    float4 v = *(const float4*)(in + (size_t)i * 4);
    float4 s4 = make_float4(0.f, 0.f, 0.f, 0.f);
    if (sc) s4 = *(const float4*)(sc + (size_t)i * 4);
    float vv[4] = {v.x, v.y, v.z, v.w};
    float ss[4] = {s4.x, s4.y, s4.z, s4.w};
    float o[4];
    const float invN = 1.0f / (float)NN;
#pragma unroll
    for (int j = 0; j < 4; j++) {
        int c = c0 + j;
        float mu  = g_stats[c] * invN;
        float var = g_stats[64 + c] * invN - mu * mu;
        float isd = rsqrtf(var + 1e-5f);
        float y = (vv[j] - mu) * isd * gam[c] + bet[c];
        y = (y > 0.0f) ? y : 0.01f * y;
        o[j] = y + ss[j];
    }
    *(float4*)(oh + (size_t)i * 4) = make_float4(o[0], o[1], o[2], o[3]);
    if (oh16)
        ((uint2*)oh16)[i] = pack_half4(o[0], o[1], o[2], o[3]);
}

// ---------------- segment max pooling (batch is sorted) ----------------
__device__ __forceinline__ void atomicMaxFloat(float* addr, float v) {
    if (v >= 0.0f) atomicMax((int*)addr, __float_as_int(v));
    else           atomicMin((unsigned int*)addr, __float_as_uint(v));
}

__global__ void pool_kernel(const float* __restrict__ h, const void* __restrict__ batch) {
    int tid = blockIdx.x * blockDim.x + threadIdx.x;
    int c = tid & 63;
    int chunk = tid >> 6;
    if (chunk >= (NN + 63) / 64) return;
    int n0 = chunk * 64;
    int n1 = (n0 + 64 < NN) ? (n0 + 64) : NN;
    int curg = -1;
    float curm = 0.0f;
    for (int n = n0; n < n1; n++) {
        int g = load_idx(batch, n);
        if ((unsigned)g >= GG) continue;
        float v = h[(size_t)n * 64 + c];
        if (g != curg) {
            if (curg >= 0) atomicMaxFloat(&g_pool[curg * 64 + c], curm);
            curg = g;
            curm = v;
        } else {
            curm = fmaxf(curm, v);
        }
    }
    if (curg >= 0) atomicMaxFloat(&g_pool[curg * 64 + c], curm);
}

// ---------------- final GEMV [G,H]@[H,1] + b ----------------
__global__ void final_kernel(const float* __restrict__ wlin, const float* __restrict__ blin,
                             float* __restrict__ outp)
{
    int g = threadIdx.x;
    if (g < GG) {
        float s = blin[0];
#pragma unroll
        for (int k = 0; k < HH; k++) s = fmaf(g_pool[g * 64 + k], wlin[k], s);
        outp[g] = s;
    }
}

// ---------------- launch ----------------
extern "C" void kernel_launch(void* const* d_in, const int* in_sizes, int n_in,
                              void* d_out, int out_size)
{
    const float* x       = (const float*)d_in[0];
    const void*  ei      = d_in[1];
    const void*  bat     = d_in[2];
    const float* w1  = (const float*)d_in[3];
    const float* b1  = (const float*)d_in[4];
    const float* w2  = (const float*)d_in[5];
    const float* b2  = (const float*)d_in[6];
    const float* w3  = (const float*)d_in[7];
    const float* b3  = (const float*)d_in[8];
    const float* g1  = (const float*)d_in[9];
    const float* be1 = (const float*)d_in[10];
    const float* g2  = (const float*)d_in[11];
    const float* be2 = (const float*)d_in[12];
    const float* g3  = (const float*)d_in[13];
    const float* be3 = (const float*)d_in[14];
    const float* wsc = (const float*)d_in[15];
    const float* bsc = (const float*)d_in[16];
    const float* wl  = (const float*)d_in[17];
    const float* bl  = (const float*)d_in[18];
    float* outp = (float*)d_out;

    float *p_t1, *p_ts, *p_out, *p_h, *p_sc;
    __half *p_a16, *p_b16;
    cudaGetSymbolAddress((void**)&p_t1,  g_t1);
    cudaGetSymbolAddress((void**)&p_ts,  g_ts);
    cudaGetSymbolAddress((void**)&p_out, g_outb);
    cudaGetSymbolAddress((void**)&p_h,   g_h);
    cudaGetSymbolAddress((void**)&p_sc,  g_sc);
    cudaGetSymbolAddress((void**)&p_a16, g_f16a);
    cudaGetSymbolAddress((void**)&p_b16, g_f16b);

    const int smem3 = (3 * 4608 + 128 * 68 + 128) * (int)sizeof(float);
    const int smem1 = (1 * 4608 + 128 * 68 + 128) * (int)sizeof(float);
    cudaFuncSetAttribute(gemm_kernel<3, true>,  cudaFuncAttributeMaxDynamicSharedMemorySize, smem3);
    cudaFuncSetAttribute(gemm_kernel<1, false>, cudaFuncAttributeMaxDynamicSharedMemorySize, smem1);

    const int TB = 256;
    const int gridN  = (NN + TB - 1) / TB;
    const int gridE  = (EE + TB - 1) / TB;
    const int gridP  = (NN * 32 + TB - 1) / TB;       // warp per node
    const int gridG  = (NN + 127) / 128;              // gemm tiles
    const int gridNm = (NN * 16 + TB - 1) / TB;       // normalize (float4)
    const int gridPl = (((NN + 63) / 64) * 64 + TB - 1) / TB;

    // graph structure (recomputed every launch; deterministic work)
    init_kernel<<<gridN, TB>>>(ei);                    // 1 (detect + flag reset)
    hist_kernel<<<gridE, TB>>>(ei, x);                 // 2 (+ x -> fp16 mirror)
    scan_kernel<<<SCAN_NB, 256>>>();                   // 3 (dis + cnt reset folded in)
    scatter_kernel<<<gridE, TB>>>(ei);                 // 4

    // layer 1 (input x; fp16 mirror in p_a16)
    prop_kernel<true ><<<gridP, TB>>>(p_a16, p_t1, p_b16);
    prop_kernel<false><<<gridP, TB>>>(p_b16, p_ts, nullptr);
    gemm_kernel<3, true><<<gridG, TB, smem3>>>(x, p_t1, p_ts, w1, b1, p_out);
    norm_kernel<<<gridNm, TB>>>(p_out, g1, be1, nullptr, p_h, p_a16);

    // layer 2
    prop_kernel<true ><<<gridP, TB>>>(p_a16, p_t1, p_b16);
    prop_kernel<false><<<gridP, TB>>>(p_b16, p_ts, nullptr);
    gemm_kernel<3, true><<<gridG, TB, smem3>>>(p_h, p_t1, p_ts, w2, b2, p_out);
    norm_kernel<<<gridNm, TB>>>(p_out, g2, be2, nullptr, p_h, p_a16);

    // layer 3 (+ shortcut)
    prop_kernel<true ><<<gridP, TB>>>(p_a16, p_t1, p_b16);
    prop_kernel<false><<<gridP, TB>>>(p_b16, p_ts, nullptr);
    gemm_kernel<3, true><<<gridG, TB, smem3>>>(p_h, p_t1, p_ts, w3, b3, p_out);
    gemm_kernel<1, false><<<gridG, TB, smem1>>>(x, x, x, wsc, bsc, p_sc);
    norm_kernel<<<gridNm, TB>>>(p_out, g3, be3, p_sc, p_h, nullptr);

    // pool + head
    pool_kernel<<<gridPl, TB>>>(p_h, bat);
    final_kernel<<<1, 64>>>(wl, bl, outp);
}